// round 14
// baseline (speedup 1.0000x reference)
#include <cuda_runtime.h>
#include <cuda_fp16.h>
#include <math.h>
#include <stdint.h>

#define BATCH 4
#define SEQ   2048
#define DIM   768
#define NH    12
#define HDIM  64
#define FFDIM (4*DIM)
#define ROWS  (BATCH*SEQ)   /* 8192 */
#define RD    ((size_t)ROWS*DIM)

// ---------------- scratch (no cudaMalloc allowed) ----------------
__device__ __half   g_x16[(size_t)ROWS*DIM];
__device__ unsigned g_wq[(size_t)(DIM/2)*DIM];
__device__ unsigned g_wk[(size_t)(DIM/2)*DIM];
__device__ unsigned g_wv[(size_t)(DIM/2)*DIM];
__device__ unsigned g_wo[(size_t)(DIM/2)*DIM];
__device__ unsigned g_w1[(size_t)(DIM/2)*FFDIM];
__device__ unsigned g_w2[(size_t)(FFDIM/2)*DIM];
__device__ __half   g_q16[(size_t)ROWS*DIM];
__device__ __half   g_k16[(size_t)ROWS*DIM];
__device__ __half   g_v16[(size_t)ROWS*DIM];
__device__ __half   g_attn16[(size_t)ROWS*DIM];
__device__ __half   g_h16[(size_t)ROWS*DIM];
__device__ __half   g_ff16[(size_t)ROWS*FFDIM];
__device__ float    g_t1[2*(size_t)ROWS*DIM];    /* two split-K partials */
__device__ float    g_h[(size_t)ROWS*DIM];

// ---------------- helpers ----------------
__device__ __forceinline__ unsigned hpack(float lo, float hi) {
    unsigned r;
    asm("cvt.rn.f16x2.f32 %0, %1, %2;" : "=r"(r) : "f"(hi), "f"(lo));
    return r;
}
__device__ __forceinline__ uint32_t smem_u32(const void* p) {
    uint32_t a;
    asm("{ .reg .u64 t; cvta.to.shared.u64 t, %1; cvt.u32.u64 %0, t; }" : "=r"(a) : "l"(p));
    return a;
}
__device__ __forceinline__ void ldsm4(unsigned* d, uint32_t addr) {
    asm volatile("ldmatrix.sync.aligned.m8n8.x4.shared.b16 {%0,%1,%2,%3}, [%4];"
                 : "=r"(d[0]), "=r"(d[1]), "=r"(d[2]), "=r"(d[3]) : "r"(addr));
}
__device__ __forceinline__ void ldsm4t(unsigned* d, uint32_t addr) {
    asm volatile("ldmatrix.sync.aligned.m8n8.x4.trans.shared.b16 {%0,%1,%2,%3}, [%4];"
                 : "=r"(d[0]), "=r"(d[1]), "=r"(d[2]), "=r"(d[3]) : "r"(addr));
}
__device__ __forceinline__ void cpa16(uint32_t dst, const void* src) {
    asm volatile("cp.async.cg.shared.global [%0], [%1], 16;" :: "r"(dst), "l"(src));
}
#define CPA_COMMIT() asm volatile("cp.async.commit_group;" ::: "memory")
#define CPA_WAIT(n)  asm volatile("cp.async.wait_group %0;" :: "n"(n) : "memory")

__device__ __forceinline__ void mma_fp16(float* d, const unsigned* a, const unsigned* b) {
    asm volatile(
        "mma.sync.aligned.m16n8k16.row.col.f32.f16.f16.f32 "
        "{%0,%1,%2,%3}, {%4,%5,%6,%7}, {%8,%9}, {%0,%1,%2,%3};\n"
        : "+f"(d[0]), "+f"(d[1]), "+f"(d[2]), "+f"(d[3])
        : "r"(a[0]), "r"(a[1]), "r"(a[2]), "r"(a[3]), "r"(b[0]), "r"(b[1]));
}

// ---------------- fused prep kernel (1D flattened tasks) ----------------
#define PREP_BLOCKS 9600

__global__ __launch_bounds__(256) void prep(const float* __restrict__ x, __half* __restrict__ x16,
                                            const float* __restrict__ Wq, const float* __restrict__ Wk,
                                            const float* __restrict__ Wv, const float* __restrict__ Wo,
                                            unsigned* oq, unsigned* ok, unsigned* ov, unsigned* oo,
                                            const float* __restrict__ W1, unsigned* o1,
                                            const float* __restrict__ W2, unsigned* o2)
{
    const int bid = blockIdx.x;
    const int tid = threadIdx.x;
    if (bid < 6144) {
        const size_t i = (size_t)bid * 256 + tid;
        float4 v = ((const float4*)x)[i];
        ((uint2*)x16)[i] = make_uint2(hpack(v.x, v.y), hpack(v.z, v.w));
        return;
    }
    const float* W; unsigned* O; int N; int idx;
    if (bid < 7296) {
        const int base = bid - 6144;
        const int z = base / 288;
        W = (z == 0) ? Wq : (z == 1) ? Wk : (z == 2) ? Wv : Wo;
        O = (z == 0) ? oq : (z == 1) ? ok : (z == 2) ? ov : oo;
        N = DIM;
        idx = (base % 288) * 256 + tid;
    } else if (bid < 8448) {
        W = W1; O = o1; N = FFDIM;
        idx = (bid - 7296) * 256 + tid;
    } else {
        W = W2; O = o2; N = DIM;
        idx = (bid - 8448) * 256 + tid;
    }
    const int kp = idx / (N / 4);
    const int nq = (idx % (N / 4)) * 4;
    float4 a = *(const float4*)&W[(size_t)(2 * kp) * N + nq];
    float4 b = *(const float4*)&W[(size_t)(2 * kp + 1) * N + nq];
    *(uint4*)&O[(size_t)kp * N + nq] =
        make_uint4(hpack(a.x, b.x), hpack(a.y, b.y), hpack(a.z, b.z), hpack(a.w, b.w));
}

// ======================================================================
// FP16 GEMM, cp.async 3-stage.
// MODE 1: plain fp16 out  2: gelu fp16  4: raw fp32 partial (split-K)
// lda = A row stride (elements); K = loop depth.
// ======================================================================
#define SB2 136

template<int MODE, int BM>
__device__ __forceinline__ void gemm_core(const __half* __restrict__ A,
                                          const unsigned* __restrict__ Bw,
                                          const float* __restrict__ bias,
                                          void* __restrict__ Cv,
                                          int N, int K, int lda,
                                          int bm, int bn, char* sm)
{
    constexpr int MT   = BM / 32;
    constexpr int ASTG = BM * 80;
    constexpr int BSTG = 16 * 544;
    constexpr int STG  = ASTG + BSTG;

    const uint32_t sb = smem_u32(sm);
    const int tid  = threadIdx.x;
    const int lane = tid & 31;
    const int warp = tid >> 5;
    const int wr   = warp >> 2;
    const int wn   = warp & 3;
    const int r0   = lane >> 2;
    const int kq   = lane & 3;

    const uint32_t aoff = (uint32_t)(wr * (BM / 2) + (lane & 7) + ((lane >> 3) & 1) * 8) * 80u
                        + (uint32_t)((lane >> 4) & 1) * 16u;

    const int ar = (BM == 128) ? (tid >> 1) : (tid >> 2);
    const int ac = (BM == 128) ? ((tid & 1) * 2) : (tid & 3);
    const int br = tid >> 4;
    const int bc = (tid & 15) * 2;

    float acc[MT][4][4];
#pragma unroll
    for (int mt = 0; mt < MT; ++mt)
#pragma unroll
        for (int nt = 0; nt < 4; ++nt)
#pragma unroll
            for (int e = 0; e < 4; ++e) acc[mt][nt][e] = 0.f;

    const int nk = K >> 5;

    auto issue = [&](int s, int t) {
        const __half* as = A + (size_t)(bm + ar) * lda + t * 32 + ac * 8;
        uint32_t ad = sb + (uint32_t)(s * STG) + (uint32_t)(ar * 80 + ac * 16);
        cpa16(ad, as);
        if (BM == 128) cpa16(ad + 16, as + 8);
        const unsigned* bs = Bw + (size_t)(t * 16 + br) * N + bn + bc * 4;
        uint32_t bd = sb + (uint32_t)(s * STG + ASTG) + (uint32_t)(br * 544 + bc * 16);
        cpa16(bd, bs);
        cpa16(bd + 16, bs + 4);
    };

    issue(0, 0); CPA_COMMIT();
    issue(1, 1); CPA_COMMIT();

    for (int t = 0; t < nk; ++t) {
        if (t + 1 < nk) { CPA_WAIT(1); } else { CPA_WAIT(0); }
        __syncthreads();
        if (t + 2 < nk) { issue((t + 2) % 3, t + 2); CPA_COMMIT(); }

        const unsigned* Bs = (const unsigned*)(sm + (t % 3) * STG + ASTG);
        const uint32_t a32 = sb + (uint32_t)((t % 3) * STG) + aoff;
#pragma unroll
        for (int kc = 0; kc < 2; ++kc) {
            const int e = kc * 8 + kq;
            unsigned af[MT][4], bf[4][2];
#pragma unroll
            for (int mt = 0; mt < MT; ++mt)
                ldsm4(af[mt], a32 + (uint32_t)(mt * 16 * 80) + (uint32_t)(kc * 32));
#pragma unroll
            for (int nt = 0; nt < 4; ++nt) {
                const int n0 = wn * 32 + nt * 8 + r0;
                bf[nt][0] = Bs[e * SB2 + n0];
                bf[nt][1] = Bs[(e + 4) * SB2 + n0];
            }
#pragma unroll
            for (int mt = 0; mt < MT; ++mt)
#pragma unroll
                for (int nt = 0; nt < 4; ++nt)
                    mma_fp16(acc[mt][nt], af[mt], bf[nt]);
        }
    }

#pragma unroll
    for (int mt = 0; mt < MT; ++mt) {
        const int row_lo = bm + wr * (BM / 2) + mt * 16 + r0;
#pragma unroll
        for (int nt = 0; nt < 4; ++nt) {
            const int col = bn + wn * 32 + nt * 8 + kq * 2;
#pragma unroll
            for (int half_ = 0; half_ < 2; ++half_) {
                const int row = row_lo + half_ * 8;
                if (MODE == 4) {
                    *(float2*)&((float*)Cv)[(size_t)row * N + col] =
                        make_float2(acc[mt][nt][half_ * 2 + 0], acc[mt][nt][half_ * 2 + 1]);
                } else {
                    float vx = acc[mt][nt][half_ * 2 + 0] + bias[col];
                    float vy = acc[mt][nt][half_ * 2 + 1] + bias[col + 1];
                    if (MODE == 2) {
                        vx = 0.5f * vx * (1.f + erff(vx * 0.70710678118654752f));
                        vy = 0.5f * vy * (1.f + erff(vy * 0.70710678118654752f));
                    }
                    ((unsigned*)Cv)[((size_t)row * N + col) >> 1] = hpack(vx, vy);
                }
            }
        }
    }
}

#define GS128 (3 * (128*80 + 16*544))   /* 56832 */

template<int MODE, int BM>
__global__ __launch_bounds__(256) void tg(const __half* __restrict__ A,
                                          const unsigned* __restrict__ Bw,
                                          const float* __restrict__ bias,
                                          void* __restrict__ C,
                                          int N, int K)
{
    extern __shared__ char smg[];
    gemm_core<MODE, BM>(A, Bw, bias, C, N, K, K,
                        blockIdx.y * BM, blockIdx.x * 128, smg);
}

// split-K GEMM: blockIdx.z selects K-half; raw fp32 partial out
__global__ __launch_bounds__(256) void tgsk(const __half* __restrict__ A,
                                            const unsigned* __restrict__ Bw,
                                            float* __restrict__ C,
                                            int N, int K)
{
    extern __shared__ char smg[];
    const int half = K >> 1;
    const int z = blockIdx.z;
    gemm_core<4, 128>(A + (size_t)z * half,
                      Bw + (size_t)z * (half >> 1) * N,
                      nullptr,
                      C + (size_t)z * RD,
                      N, half, K,
                      blockIdx.y * 128, blockIdx.x * 128, smg);
}

// fused QKV (outputs in natural [B,S,D] fp16): grid.x = 18
__global__ __launch_bounds__(256) void qkv16(const __half* __restrict__ A,
                                             const unsigned* __restrict__ wq,
                                             const unsigned* __restrict__ wk,
                                             const unsigned* __restrict__ wv,
                                             const float* __restrict__ bq,
                                             const float* __restrict__ bk,
                                             const float* __restrict__ bv,
                                             __half* q, __half* k, __half* v)
{
    extern __shared__ char smg[];
    const int sel = blockIdx.x / 6;
    const int bxl = blockIdx.x % 6;
    const unsigned* B = (sel == 0) ? wq : (sel == 1) ? wk : wv;
    const float* bias = (sel == 0) ? bq : (sel == 1) ? bk : bv;
    __half*      C    = (sel == 0) ? q  : (sel == 1) ? k  : v;
    gemm_core<1, 128>(A, B, bias, C, DIM, DIM, DIM,
                      blockIdx.y * 128, bxl * 128, smg);
}

// ======================================================================
// FP16 flash attention (R13-proven): cp.async 3-stage, static-max h2exp2
// softmax, P in registers, ldmatrix K (non-trans) + V (trans).
// ======================================================================
#define KSTG 9216
#define ATT_STG (2 * KSTG)
#define ATT_MB  (3 * ATT_STG)
#define ATT_SMEM (3 * ATT_STG + 4096)
#define CSCALE 0.18033688011112042f   /* 0.125 * log2(e) */

__global__ __launch_bounds__(256, 2) void attn_tc(const __half* __restrict__ q,
                                                  const __half* __restrict__ k,
                                                  const __half* __restrict__ v,
                                                  const int* __restrict__ mask,
                                                  __half* __restrict__ out)
{
    extern __shared__ char smc[];
    const uint32_t sb = smem_u32(smc);
    half2* mb2 = (half2*)(smc + ATT_MB);

    const int tid  = threadIdx.x;
    const int lane = tid & 31;
    const int warp = tid >> 5;

    const int qtile = blockIdx.x & 15;
    const int bh    = blockIdx.x >> 4;
    const int b     = bh / NH;
    const int h     = bh % NH;

    const int q0 = qtile * 128;

    const int r0 = lane >> 2;
    const int kq = lane & 3;

    const int kr  = tid & 63;
    const int kc2 = tid >> 6;

    const uint32_t koff = (uint32_t)((lane & 7) + ((lane >> 4) & 1) * 8) * 144u
                        + (uint32_t)((lane >> 3) & 1) * 16u;
    const uint32_t voff = (uint32_t)((lane & 7) + ((lane >> 3) & 1) * 8) * 144u
                        + (uint32_t)((lane >> 4) & 1) * 16u;

    for (int i = tid; i < SEQ / 2; i += 256) {
        int2 mv = ((const int2*)(mask + b * SEQ))[i];
        mb2[i] = __floats2half2_rn(mv.x ? 0.f : -1e30f, mv.y ? 0.f : -1e30f);
    }

    unsigned qa[4][4];
    {
        const __half* qp = q + (size_t)(b * SEQ + q0 + warp * 16) * DIM + h * HDIM;
#pragma unroll
        for (int kc = 0; kc < 4; ++kc) {
            const int c0 = kc * 16 + kq * 2;
            qa[kc][0] = *(const unsigned*)(qp + (size_t)r0 * DIM + c0);
            qa[kc][1] = *(const unsigned*)(qp + (size_t)(r0 + 8) * DIM + c0);
            qa[kc][2] = *(const unsigned*)(qp + (size_t)r0 * DIM + c0 + 8);
            qa[kc][3] = *(const unsigned*)(qp + (size_t)(r0 + 8) * DIM + c0 + 8);
        }
    }

    float ls0 = 0.f, ls1 = 0.f;
    float oacc[8][4];
#pragma unroll
    for (int nt = 0; nt < 8; ++nt)
#pragma unroll
        for (int e = 0; e < 4; ++e) oacc[nt][e] = 0.f;

    auto issue = [&](int s, int kt) {
        const __half* ks = k + (size_t)(b * SEQ + kt * 64 + kr) * DIM + h * HDIM + kc2 * 16;
        uint32_t kd = sb + (uint32_t)(s * ATT_STG) + (uint32_t)(kr * 144 + kc2 * 32);
        cpa16(kd, ks);
        cpa16(kd + 16, ks + 8);
        const __half* vs = v + (size_t)(b * SEQ + kt * 64 + kr) * DIM + h * HDIM + kc2 * 16;
        uint32_t vd = kd + KSTG;
        cpa16(vd, vs);
        cpa16(vd + 16, vs + 8);
    };

    const int NT = SEQ / 64;   // 32
    issue(0, 0); CPA_COMMIT();
    issue(1, 1); CPA_COMMIT();

    for (int kt = 0; kt < NT; ++kt) {
        if (kt + 1 < NT) { CPA_WAIT(1); } else { CPA_WAIT(0); }
        __syncthreads();
        if (kt + 2 < NT) { issue((kt + 2) % 3, kt + 2); CPA_COMMIT(); }

        const uint32_t kb = sb + (uint32_t)((kt % 3) * ATT_STG);
        const uint32_t vb = kb + KSTG;

        float sf[8][4];
#pragma unroll
        for (int nt = 0; nt < 8; ++nt)
#pragma unroll
            for (int e = 0; e < 4; ++e) sf[nt][e] = 0.f;

#pragma unroll
        for (int np = 0; np < 4; ++np) {
#pragma unroll
            for (int kc = 0; kc < 4; ++kc) {
                unsigned b4[4];
                ldsm4(b4, kb + koff + (uint32_t)(np * 2304) + (uint32_t)(kc * 32));
                mma_fp16(sf[2 * np],     qa[kc], b4);
                mma_fp16(sf[2 * np + 1], qa[kc], b4 + 2);
            }
        }

        const half2* mt = mb2 + kt * 32;
        unsigned pa[4][4];
        half2 l2a = __floats2half2_rn(0.f, 0.f);
        half2 l2b = l2a;
#pragma unroll
        for (int kc = 0; kc < 4; ++kc) {
#pragma unroll
            for (int j = 0; j < 2; ++j) {
                const int nt = 2 * kc + j;
                const half2 bias = mt[nt * 4 + kq];
                half2 p0 = h2exp2(__hadd2(
                    __floats2half2_rn(sf[nt][0] * CSCALE, sf[nt][1] * CSCALE), bias));
                half2 p1 = h2exp2(__hadd2(
                    __floats2half2_rn(sf[nt][2] * CSCALE, sf[nt][3] * CSCALE), bias));
                pa[kc][2 * j]     = *(unsigned*)&p0;
                pa[kc][2 * j + 1] = *(unsigned*)&p1;
                l2a = __hadd2(l2a, p0);
                l2b = __hadd2(l2b, p1);
            }
        }
        {
            float2 fa = __half22float2(l2a), fb = __half22float2(l2b);
            ls0 += fa.x + fa.y;
            ls1 += fb.x + fb.y;
        }

#pragma unroll
        for (int ntA = 0; ntA < 8; ntA += 2) {
#pragma unroll
            for (int kc = 0; kc < 4; ++kc) {
                unsigned v4[4];
                ldsm4t(v4, vb + voff + (uint32_t)(kc * 16 * 144) + (uint32_t)(ntA * 16));
                mma_fp16(oacc[ntA],     pa[kc], v4);
                mma_fp16(oacc[ntA + 1], pa[kc], v4 + 2);
            }
        }
    }

    ls0 += __shfl_xor_sync(0xffffffffu, ls0, 1);
    ls0 += __shfl_xor_sync(0xffffffffu, ls0, 2);
    ls1 += __shfl_xor_sync(0xffffffffu, ls1, 1);
    ls1 += __shfl_xor_sync(0xffffffffu, ls1, 2);
    const float inv0 = 1.f / ls0;
    const float inv1 = 1.f / ls1;
    const int row_g = q0 + warp * 16 + r0;
    unsigned* o32 = (unsigned*)out;
#pragma unroll
    for (int nt = 0; nt < 8; ++nt) {
        const int col = h * HDIM + nt * 8 + kq * 2;
        o32[((size_t)(b * SEQ + row_g) * DIM + col) >> 1] =
            hpack(oacc[nt][0] * inv0, oacc[nt][1] * inv0);
        o32[((size_t)(b * SEQ + row_g + 8) * DIM + col) >> 1] =
            hpack(oacc[nt][2] * inv1, oacc[nt][3] * inv1);
    }
}

// ---------------- fused LayerNorm: in = p0 + p1 + res + bias ----------------
template<int H16>
__global__ __launch_bounds__(256) void ln_fuse(const float* __restrict__ p0,
                                               const float* __restrict__ p1,
                                               const float* __restrict__ res,
                                               const float* __restrict__ bias,
                                               const float* __restrict__ gam,
                                               const float* __restrict__ bet,
                                               float* __restrict__ out,
                                               __half* __restrict__ out16)
{
    const int warp = threadIdx.x >> 5;
    const int lane = threadIdx.x & 31;
    const int row  = blockIdx.x * 8 + warp;
    const size_t rb = (size_t)row * DIM;

    float4 v[6];
    float s = 0.f, s2 = 0.f;
#pragma unroll
    for (int i = 0; i < 6; ++i) {
        const int d = lane * 4 + i * 128;
        float4 a = *(const float4*)&p0[rb + d];
        float4 b = *(const float4*)&p1[rb + d];
        float4 r = *(const float4*)&res[rb + d];
        float4 bi = *(const float4*)&bias[d];
        v[i].x = a.x + b.x + r.x + bi.x;
        v[i].y = a.y + b.y + r.y + bi.y;
        v[i].z = a.z + b.z + r.z + bi.z;
        v[i].w = a.w + b.w + r.w + bi.w;
        s  += v[i].x + v[i].y + v[i].z + v[i].w;
        s2 += v[i].x * v[i].x + v[i].y * v[i].y + v[i].z * v[i].z + v[i].w * v[i].w;
    }
#pragma unroll
    for (int o = 16; o > 0; o >>= 1) {
        s  += __shfl_xor_sync(0xffffffffu, s,  o);
        s2 += __shfl_xor_sync(0xffffffffu, s2, o);
    }
    const float mu   = s * (1.f / DIM);
    const float rstd = rsqrtf(s2 * (1.f / DIM) - mu * mu + 1e-6f);

#pragma unroll
    for (int i = 0; i < 6; ++i) {
        const int d = lane * 4 + i * 128;
        float4 g = *(const float4*)&gam[d];
        float4 be = *(const float4*)&bet[d];
        float4 r;
        r.x = (v[i].x - mu) * rstd * g.x + be.x;
        r.y = (v[i].y - mu) * rstd * g.y + be.y;
        r.z = (v[i].z - mu) * rstd * g.z + be.z;
        r.w = (v[i].w - mu) * rstd * g.w + be.w;
        *(float4*)&out[rb + d] = r;
        if (H16) {
            uint2 u = make_uint2(hpack(r.x, r.y), hpack(r.z, r.w));
            ((uint2*)out16)[(rb + d) >> 2] = u;
        }
    }
}

// ---------------- launch ----------------
extern "C" void kernel_launch(void* const* d_in, const int* in_sizes, int n_in,
                              void* d_out, int out_size)
{
    const float* x    = (const float*)d_in[0];
    const int*   mask = (const int*)  d_in[1];
    const float* Wq   = (const float*)d_in[2];
    const float* bq   = (const float*)d_in[3];
    const float* Wk   = (const float*)d_in[4];
    const float* bk   = (const float*)d_in[5];
    const float* Wv   = (const float*)d_in[6];
    const float* bv   = (const float*)d_in[7];
    const float* Wo   = (const float*)d_in[8];
    const float* bo   = (const float*)d_in[9];
    const float* W1   = (const float*)d_in[10];
    const float* b1   = (const float*)d_in[11];
    const float* W2   = (const float*)d_in[12];
    const float* b2   = (const float*)d_in[13];
    const float* g1   = (const float*)d_in[14];
    const float* be1  = (const float*)d_in[15];
    const float* g2   = (const float*)d_in[16];
    const float* be2  = (const float*)d_in[17];
    float* out = (float*)d_out;

    __half *x16, *q16, *k16, *v16, *attn16, *h16, *ff16;
    unsigned *wq, *wk, *wv, *wo, *w1, *w2;
    float *t1, *h;
    cudaGetSymbolAddress((void**)&x16,    g_x16);
    cudaGetSymbolAddress((void**)&q16,    g_q16);
    cudaGetSymbolAddress((void**)&k16,    g_k16);
    cudaGetSymbolAddress((void**)&v16,    g_v16);
    cudaGetSymbolAddress((void**)&attn16, g_attn16);
    cudaGetSymbolAddress((void**)&h16,    g_h16);
    cudaGetSymbolAddress((void**)&ff16,   g_ff16);
    cudaGetSymbolAddress((void**)&wq,     g_wq);
    cudaGetSymbolAddress((void**)&wk,     g_wk);
    cudaGetSymbolAddress((void**)&wv,     g_wv);
    cudaGetSymbolAddress((void**)&wo,     g_wo);
    cudaGetSymbolAddress((void**)&w1,     g_w1);
    cudaGetSymbolAddress((void**)&w2,     g_w2);
    cudaGetSymbolAddress((void**)&t1,     g_t1);
    cudaGetSymbolAddress((void**)&h,      g_h);

    static bool attr_done = false;
    if (!attr_done) {
        cudaFuncSetAttribute(qkv16,      cudaFuncAttributeMaxDynamicSharedMemorySize, GS128);
        cudaFuncSetAttribute(tg<2,128>,  cudaFuncAttributeMaxDynamicSharedMemorySize, GS128);
        cudaFuncSetAttribute(tgsk,       cudaFuncAttributeMaxDynamicSharedMemorySize, GS128);
        cudaFuncSetAttribute(attn_tc,    cudaFuncAttributeMaxDynamicSharedMemorySize, ATT_SMEM);
        attr_done = true;
    }

    // fused conversions / packing
    prep<<<PREP_BLOCKS, 256>>>(x, x16, Wq, Wk, Wv, Wo, wq, wk, wv, wo, W1, w1, W2, w2);

    // fused QKV -> fp16 [B,S,D]
    qkv16<<<dim3(18, ROWS / 128), 256, GS128>>>(x16, wq, wk, wv, bq, bk, bv, q16, k16, v16);

    // fp16 flash attention -> fp16 [B,S,D]
    attn_tc<<<BATCH * NH * (SEQ / 128), 256, ATT_SMEM>>>(q16, k16, v16, mask, attn16);

    // O projection split-K (partials), LN1 fused add (p0+p1+x+bo)
    tgsk<<<dim3(DIM / 128, ROWS / 128, 2), 256, GS128>>>(attn16, wo, t1, DIM, DIM);
    ln_fuse<1><<<ROWS / 8, 256>>>(t1, t1 + RD, x, bo, g1, be1, h, h16);

    // FFN1 (gelu, fp16 out)
    tg<2,128><<<dim3(FFDIM / 128, ROWS / 128), 256, GS128>>>(h16, w1, b1, ff16, FFDIM, DIM);

    // FFN2 split-K (partials), LN2 fused add (p0+p1+h+b2)
    tgsk<<<dim3(DIM / 128, ROWS / 128, 2), 256, GS128>>>(ff16, w2, t1, DIM, FFDIM);
    ln_fuse<0><<<ROWS / 8, 256>>>(t1, t1 + RD, h, b2, g2, be2, out, nullptr);
}

// round 15
// speedup vs baseline: 1.0179x; 1.0179x over previous
#include <cuda_runtime.h>
#include <cuda_fp16.h>
#include <math.h>
#include <stdint.h>

#define BATCH 4
#define SEQ   2048
#define DIM   768
#define NH    12
#define HDIM  64
#define FFDIM (4*DIM)
#define ROWS  (BATCH*SEQ)   /* 8192 */

// ---------------- scratch (no cudaMalloc allowed) ----------------
__device__ __half   g_x16[(size_t)ROWS*DIM];
__device__ unsigned g_wq[(size_t)(DIM/2)*DIM];
__device__ unsigned g_wk[(size_t)(DIM/2)*DIM];
__device__ unsigned g_wv[(size_t)(DIM/2)*DIM];
__device__ unsigned g_wo[(size_t)(DIM/2)*DIM];
__device__ unsigned g_w1[(size_t)(DIM/2)*FFDIM];
__device__ unsigned g_w2[(size_t)(FFDIM/2)*DIM];
__device__ __half   g_q16[(size_t)ROWS*DIM];
__device__ __half   g_k16[(size_t)ROWS*DIM];
__device__ __half   g_v16[(size_t)ROWS*DIM];
__device__ __half   g_attn16[(size_t)ROWS*DIM];
__device__ __half   g_h16[(size_t)ROWS*DIM];
__device__ __half   g_ff16[(size_t)ROWS*FFDIM];
__device__ float    g_t1[(size_t)ROWS*DIM];
__device__ float    g_h[(size_t)ROWS*DIM];

// ---------------- helpers ----------------
__device__ __forceinline__ unsigned hpack(float lo, float hi) {
    unsigned r;
    asm("cvt.rn.f16x2.f32 %0, %1, %2;" : "=r"(r) : "f"(hi), "f"(lo));
    return r;
}
__device__ __forceinline__ uint32_t smem_u32(const void* p) {
    uint32_t a;
    asm("{ .reg .u64 t; cvta.to.shared.u64 t, %1; cvt.u32.u64 %0, t; }" : "=r"(a) : "l"(p));
    return a;
}
__device__ __forceinline__ void ldsm4(unsigned* d, uint32_t addr) {
    asm volatile("ldmatrix.sync.aligned.m8n8.x4.shared.b16 {%0,%1,%2,%3}, [%4];"
                 : "=r"(d[0]), "=r"(d[1]), "=r"(d[2]), "=r"(d[3]) : "r"(addr));
}
__device__ __forceinline__ void ldsm4t(unsigned* d, uint32_t addr) {
    asm volatile("ldmatrix.sync.aligned.m8n8.x4.trans.shared.b16 {%0,%1,%2,%3}, [%4];"
                 : "=r"(d[0]), "=r"(d[1]), "=r"(d[2]), "=r"(d[3]) : "r"(addr));
}
__device__ __forceinline__ void cpa16(uint32_t dst, const void* src) {
    asm volatile("cp.async.cg.shared.global [%0], [%1], 16;" :: "r"(dst), "l"(src));
}
#define CPA_COMMIT() asm volatile("cp.async.commit_group;" ::: "memory")
template<int N> __device__ __forceinline__ void cpa_wait() {
    asm volatile("cp.async.wait_group %0;" :: "n"(N) : "memory");
}

__device__ __forceinline__ void mma_fp16(float* d, const unsigned* a, const unsigned* b) {
    asm volatile(
        "mma.sync.aligned.m16n8k16.row.col.f32.f16.f16.f32 "
        "{%0,%1,%2,%3}, {%4,%5,%6,%7}, {%8,%9}, {%0,%1,%2,%3};\n"
        : "+f"(d[0]), "+f"(d[1]), "+f"(d[2]), "+f"(d[3])
        : "r"(a[0]), "r"(a[1]), "r"(a[2]), "r"(a[3]), "r"(b[0]), "r"(b[1]));
}

// ---------------- fused prep kernel (1D flattened tasks) ----------------
#define PREP_BLOCKS 9600

__global__ __launch_bounds__(256) void prep(const float* __restrict__ x, __half* __restrict__ x16,
                                            const float* __restrict__ Wq, const float* __restrict__ Wk,
                                            const float* __restrict__ Wv, const float* __restrict__ Wo,
                                            unsigned* oq, unsigned* ok, unsigned* ov, unsigned* oo,
                                            const float* __restrict__ W1, unsigned* o1,
                                            const float* __restrict__ W2, unsigned* o2)
{
    const int bid = blockIdx.x;
    const int tid = threadIdx.x;
    if (bid < 6144) {
        const size_t i = (size_t)bid * 256 + tid;
        float4 v = ((const float4*)x)[i];
        ((uint2*)x16)[i] = make_uint2(hpack(v.x, v.y), hpack(v.z, v.w));
        return;
    }
    const float* W; unsigned* O; int N; int idx;
    if (bid < 7296) {
        const int base = bid - 6144;
        const int z = base / 288;
        W = (z == 0) ? Wq : (z == 1) ? Wk : (z == 2) ? Wv : Wo;
        O = (z == 0) ? oq : (z == 1) ? ok : (z == 2) ? ov : oo;
        N = DIM;
        idx = (base % 288) * 256 + tid;
    } else if (bid < 8448) {
        W = W1; O = o1; N = FFDIM;
        idx = (bid - 7296) * 256 + tid;
    } else {
        W = W2; O = o2; N = DIM;
        idx = (bid - 8448) * 256 + tid;
    }
    const int kp = idx / (N / 4);
    const int nq = (idx % (N / 4)) * 4;
    float4 a = *(const float4*)&W[(size_t)(2 * kp) * N + nq];
    float4 b = *(const float4*)&W[(size_t)(2 * kp + 1) * N + nq];
    *(uint4*)&O[(size_t)kp * N + nq] =
        make_uint4(hpack(a.x, b.x), hpack(a.y, b.y), hpack(a.z, b.z), hpack(a.w, b.w));
}

// ======================================================================
// FP16 GEMM, cp.async pipeline (STAGES = 3 for BM=128, 4 for BM=64).
// MODE 1: plain fp16 out  2: gelu fp16  3: +bias+res fp32
// ======================================================================
#define SB2 136

template<int MODE, int BM, int STAGES>
__device__ __forceinline__ void gemm_core(const __half* __restrict__ A,
                                          const unsigned* __restrict__ Bw,
                                          const float* __restrict__ bias,
                                          const float* __restrict__ res,
                                          void* __restrict__ Cv,
                                          int N, int K, int bm, int bn, char* sm)
{
    constexpr int MT   = BM / 32;
    constexpr int ASTG = BM * 80;
    constexpr int BSTG = 16 * 544;
    constexpr int STG  = ASTG + BSTG;

    const uint32_t sb = smem_u32(sm);
    const int tid  = threadIdx.x;
    const int lane = tid & 31;
    const int warp = tid >> 5;
    const int wr   = warp >> 2;
    const int wn   = warp & 3;
    const int r0   = lane >> 2;
    const int kq   = lane & 3;

    const uint32_t aoff = (uint32_t)(wr * (BM / 2) + (lane & 7) + ((lane >> 3) & 1) * 8) * 80u
                        + (uint32_t)((lane >> 4) & 1) * 16u;

    const int ar = (BM == 128) ? (tid >> 1) : (tid >> 2);
    const int ac = (BM == 128) ? ((tid & 1) * 2) : (tid & 3);
    const int br = tid >> 4;
    const int bc = (tid & 15) * 2;

    float acc[MT][4][4];
#pragma unroll
    for (int mt = 0; mt < MT; ++mt)
#pragma unroll
        for (int nt = 0; nt < 4; ++nt)
#pragma unroll
            for (int e = 0; e < 4; ++e) acc[mt][nt][e] = 0.f;

    const int nk = K >> 5;

    auto sidx = [&](int t) -> int { return (STAGES == 4) ? (t & 3) : (t % 3); };

    auto issue = [&](int s, int t) {
        const __half* as = A + (size_t)(bm + ar) * K + t * 32 + ac * 8;
        uint32_t ad = sb + (uint32_t)(s * STG) + (uint32_t)(ar * 80 + ac * 16);
        cpa16(ad, as);
        if (BM == 128) cpa16(ad + 16, as + 8);
        const unsigned* bs = Bw + (size_t)(t * 16 + br) * N + bn + bc * 4;
        uint32_t bd = sb + (uint32_t)(s * STG + ASTG) + (uint32_t)(br * 544 + bc * 16);
        cpa16(bd, bs);
        cpa16(bd + 16, bs + 4);
    };

#pragma unroll
    for (int p = 0; p < STAGES - 1; ++p) { issue(p, p); CPA_COMMIT(); }

    for (int t = 0; t < nk; ++t) {
        if (STAGES == 3) {
            if (t + 1 < nk) cpa_wait<1>(); else cpa_wait<0>();
        } else {
            if (t + 2 < nk) cpa_wait<2>();
            else if (t + 1 < nk) cpa_wait<1>();
            else cpa_wait<0>();
        }
        __syncthreads();
        if (t + STAGES - 1 < nk) { issue(sidx(t + STAGES - 1), t + STAGES - 1); CPA_COMMIT(); }

        const unsigned* Bs = (const unsigned*)(sm + sidx(t) * STG + ASTG);
        const uint32_t a32 = sb + (uint32_t)(sidx(t) * STG) + aoff;
#pragma unroll
        for (int kc = 0; kc < 2; ++kc) {
            const int e = kc * 8 + kq;
            unsigned af[MT][4], bf[4][2];
#pragma unroll
            for (int mt = 0; mt < MT; ++mt)
                ldsm4(af[mt], a32 + (uint32_t)(mt * 16 * 80) + (uint32_t)(kc * 32));
#pragma unroll
            for (int nt = 0; nt < 4; ++nt) {
                const int n0 = wn * 32 + nt * 8 + r0;
                bf[nt][0] = Bs[e * SB2 + n0];
                bf[nt][1] = Bs[(e + 4) * SB2 + n0];
            }
#pragma unroll
            for (int mt = 0; mt < MT; ++mt)
#pragma unroll
                for (int nt = 0; nt < 4; ++nt)
                    mma_fp16(acc[mt][nt], af[mt], bf[nt]);
        }
    }

#pragma unroll
    for (int mt = 0; mt < MT; ++mt) {
        const int row_lo = bm + wr * (BM / 2) + mt * 16 + r0;
#pragma unroll
        for (int nt = 0; nt < 4; ++nt) {
            const int col = bn + wn * 32 + nt * 8 + kq * 2;
            const float b0 = bias[col], b1 = bias[col + 1];
#pragma unroll
            for (int half_ = 0; half_ < 2; ++half_) {
                const int row = row_lo + half_ * 8;
                float vx = acc[mt][nt][half_ * 2 + 0] + b0;
                float vy = acc[mt][nt][half_ * 2 + 1] + b1;
                if (MODE == 2) {
                    vx = 0.5f * vx * (1.f + erff(vx * 0.70710678118654752f));
                    vy = 0.5f * vy * (1.f + erff(vy * 0.70710678118654752f));
                    ((unsigned*)Cv)[((size_t)row * N + col) >> 1] = hpack(vx, vy);
                } else if (MODE == 1) {
                    ((unsigned*)Cv)[((size_t)row * N + col) >> 1] = hpack(vx, vy);
                } else {   // MODE 3
                    float2 r = *(const float2*)&res[(size_t)row * N + col];
                    float2 o = make_float2(vx + r.x, vy + r.y);
                    *(float2*)&((float*)Cv)[(size_t)row * N + col] = o;
                }
            }
        }
    }
}

#define GS128 (3 * (128*80 + 16*544))   /* 56832 */
#define GS64  (4 * ( 64*80 + 16*544))   /* 55296: 4-stage */

template<int MODE, int BM, int STAGES>
__global__ __launch_bounds__(256) void tg(const __half* __restrict__ A,
                                          const unsigned* __restrict__ Bw,
                                          const float* __restrict__ bias,
                                          const float* __restrict__ res,
                                          void* __restrict__ C,
                                          int N, int K)
{
    extern __shared__ char smg[];
    gemm_core<MODE, BM, STAGES>(A, Bw, bias, res, C, N, K,
                                blockIdx.y * BM, blockIdx.x * 128, smg);
}

// fused QKV (outputs in natural [B,S,D] fp16): grid.x = 18
__global__ __launch_bounds__(256) void qkv16(const __half* __restrict__ A,
                                             const unsigned* __restrict__ wq,
                                             const unsigned* __restrict__ wk,
                                             const unsigned* __restrict__ wv,
                                             const float* __restrict__ bq,
                                             const float* __restrict__ bk,
                                             const float* __restrict__ bv,
                                             __half* q, __half* k, __half* v)
{
    extern __shared__ char smg[];
    const int sel = blockIdx.x / 6;
    const int bxl = blockIdx.x % 6;
    const unsigned* B = (sel == 0) ? wq : (sel == 1) ? wk : wv;
    const float* bias = (sel == 0) ? bq : (sel == 1) ? bk : bv;
    __half*      C    = (sel == 0) ? q  : (sel == 1) ? k  : v;
    gemm_core<1, 128, 3>(A, B, bias, nullptr, C, DIM, DIM,
                         blockIdx.y * 128, bxl * 128, smg);
}

// ======================================================================
// FP16 flash attention (R13-proven): cp.async 3-stage, static-max h2exp2
// softmax, P in registers, ldmatrix K (non-trans) + V (trans).
// ======================================================================
#define KSTG 9216
#define ATT_STG (2 * KSTG)
#define ATT_MB  (3 * ATT_STG)
#define ATT_SMEM (3 * ATT_STG + 4096)
#define CSCALE 0.18033688011112042f   /* 0.125 * log2(e) */

__global__ __launch_bounds__(256, 2) void attn_tc(const __half* __restrict__ q,
                                                  const __half* __restrict__ k,
                                                  const __half* __restrict__ v,
                                                  const int* __restrict__ mask,
                                                  __half* __restrict__ out)
{
    extern __shared__ char smc[];
    const uint32_t sb = smem_u32(smc);
    half2* mb2 = (half2*)(smc + ATT_MB);

    const int tid  = threadIdx.x;
    const int lane = tid & 31;
    const int warp = tid >> 5;

    const int qtile = blockIdx.x & 15;
    const int bh    = blockIdx.x >> 4;
    const int b     = bh / NH;
    const int h     = bh % NH;

    const int q0 = qtile * 128;

    const int r0 = lane >> 2;
    const int kq = lane & 3;

    const int kr  = tid & 63;
    const int kc2 = tid >> 6;

    const uint32_t koff = (uint32_t)((lane & 7) + ((lane >> 4) & 1) * 8) * 144u
                        + (uint32_t)((lane >> 3) & 1) * 16u;
    const uint32_t voff = (uint32_t)((lane & 7) + ((lane >> 3) & 1) * 8) * 144u
                        + (uint32_t)((lane >> 4) & 1) * 16u;

    for (int i = tid; i < SEQ / 2; i += 256) {
        int2 mv = ((const int2*)(mask + b * SEQ))[i];
        mb2[i] = __floats2half2_rn(mv.x ? 0.f : -1e30f, mv.y ? 0.f : -1e30f);
    }

    unsigned qa[4][4];
    {
        const __half* qp = q + (size_t)(b * SEQ + q0 + warp * 16) * DIM + h * HDIM;
#pragma unroll
        for (int kc = 0; kc < 4; ++kc) {
            const int c0 = kc * 16 + kq * 2;
            qa[kc][0] = *(const unsigned*)(qp + (size_t)r0 * DIM + c0);
            qa[kc][1] = *(const unsigned*)(qp + (size_t)(r0 + 8) * DIM + c0);
            qa[kc][2] = *(const unsigned*)(qp + (size_t)r0 * DIM + c0 + 8);
            qa[kc][3] = *(const unsigned*)(qp + (size_t)(r0 + 8) * DIM + c0 + 8);
        }
    }

    float ls0 = 0.f, ls1 = 0.f;
    float oacc[8][4];
#pragma unroll
    for (int nt = 0; nt < 8; ++nt)
#pragma unroll
        for (int e = 0; e < 4; ++e) oacc[nt][e] = 0.f;

    auto issue = [&](int s, int kt) {
        const __half* ks = k + (size_t)(b * SEQ + kt * 64 + kr) * DIM + h * HDIM + kc2 * 16;
        uint32_t kd = sb + (uint32_t)(s * ATT_STG) + (uint32_t)(kr * 144 + kc2 * 32);
        cpa16(kd, ks);
        cpa16(kd + 16, ks + 8);
        const __half* vs = v + (size_t)(b * SEQ + kt * 64 + kr) * DIM + h * HDIM + kc2 * 16;
        uint32_t vd = kd + KSTG;
        cpa16(vd, vs);
        cpa16(vd + 16, vs + 8);
    };

    const int NT = SEQ / 64;   // 32
    issue(0, 0); CPA_COMMIT();
    issue(1, 1); CPA_COMMIT();

    for (int kt = 0; kt < NT; ++kt) {
        if (kt + 1 < NT) { cpa_wait<1>(); } else { cpa_wait<0>(); }
        __syncthreads();
        if (kt + 2 < NT) { issue((kt + 2) % 3, kt + 2); CPA_COMMIT(); }

        const uint32_t kb = sb + (uint32_t)((kt % 3) * ATT_STG);
        const uint32_t vb = kb + KSTG;

        float sf[8][4];
#pragma unroll
        for (int nt = 0; nt < 8; ++nt)
#pragma unroll
            for (int e = 0; e < 4; ++e) sf[nt][e] = 0.f;

#pragma unroll
        for (int np = 0; np < 4; ++np) {
#pragma unroll
            for (int kc = 0; kc < 4; ++kc) {
                unsigned b4[4];
                ldsm4(b4, kb + koff + (uint32_t)(np * 2304) + (uint32_t)(kc * 32));
                mma_fp16(sf[2 * np],     qa[kc], b4);
                mma_fp16(sf[2 * np + 1], qa[kc], b4 + 2);
            }
        }

        const half2* mt = mb2 + kt * 32;
        unsigned pa[4][4];
        half2 l2a = __floats2half2_rn(0.f, 0.f);
        half2 l2b = l2a;
#pragma unroll
        for (int kc = 0; kc < 4; ++kc) {
#pragma unroll
            for (int j = 0; j < 2; ++j) {
                const int nt = 2 * kc + j;
                const half2 bias = mt[nt * 4 + kq];
                half2 p0 = h2exp2(__hadd2(
                    __floats2half2_rn(sf[nt][0] * CSCALE, sf[nt][1] * CSCALE), bias));
                half2 p1 = h2exp2(__hadd2(
                    __floats2half2_rn(sf[nt][2] * CSCALE, sf[nt][3] * CSCALE), bias));
                pa[kc][2 * j]     = *(unsigned*)&p0;
                pa[kc][2 * j + 1] = *(unsigned*)&p1;
                l2a = __hadd2(l2a, p0);
                l2b = __hadd2(l2b, p1);
            }
        }
        {
            float2 fa = __half22float2(l2a), fb = __half22float2(l2b);
            ls0 += fa.x + fa.y;
            ls1 += fb.x + fb.y;
        }

#pragma unroll
        for (int ntA = 0; ntA < 8; ntA += 2) {
#pragma unroll
            for (int kc = 0; kc < 4; ++kc) {
                unsigned v4[4];
                ldsm4t(v4, vb + voff + (uint32_t)(kc * 16 * 144) + (uint32_t)(ntA * 16));
                mma_fp16(oacc[ntA],     pa[kc], v4);
                mma_fp16(oacc[ntA + 1], pa[kc], v4 + 2);
            }
        }
    }

    ls0 += __shfl_xor_sync(0xffffffffu, ls0, 1);
    ls0 += __shfl_xor_sync(0xffffffffu, ls0, 2);
    ls1 += __shfl_xor_sync(0xffffffffu, ls1, 1);
    ls1 += __shfl_xor_sync(0xffffffffu, ls1, 2);
    const float inv0 = 1.f / ls0;
    const float inv1 = 1.f / ls1;
    const int row_g = q0 + warp * 16 + r0;
    unsigned* o32 = (unsigned*)out;
#pragma unroll
    for (int nt = 0; nt < 8; ++nt) {
        const int col = h * HDIM + nt * 8 + kq * 2;
        o32[((size_t)(b * SEQ + row_g) * DIM + col) >> 1] =
            hpack(oacc[nt][0] * inv0, oacc[nt][1] * inv0);
        o32[((size_t)(b * SEQ + row_g + 8) * DIM + col) >> 1] =
            hpack(oacc[nt][2] * inv1, oacc[nt][3] * inv1);
    }
}

// ---------------- LayerNorm: one warp per row; optional fp16 copy ----------------
template<int H16>
__global__ __launch_bounds__(256) void ln_kernel(const float* __restrict__ in,
                                                 const float* __restrict__ gam,
                                                 const float* __restrict__ bet,
                                                 float* __restrict__ out,
                                                 __half* __restrict__ out16)
{
    const int warp = threadIdx.x >> 5;
    const int lane = threadIdx.x & 31;
    const int row  = blockIdx.x * 8 + warp;

    const float* x = in + (size_t)row * DIM + lane * 4;

    float4 v[6];
    float s = 0.f, s2 = 0.f;
#pragma unroll
    for (int i = 0; i < 6; ++i) {
        v[i] = *(const float4*)(x + i * 128);
        s  += v[i].x + v[i].y + v[i].z + v[i].w;
        s2 += v[i].x * v[i].x + v[i].y * v[i].y + v[i].z * v[i].z + v[i].w * v[i].w;
    }
#pragma unroll
    for (int o = 16; o > 0; o >>= 1) {
        s  += __shfl_xor_sync(0xffffffffu, s,  o);
        s2 += __shfl_xor_sync(0xffffffffu, s2, o);
    }
    const float mu   = s * (1.f / DIM);
    const float rstd = rsqrtf(s2 * (1.f / DIM) - mu * mu + 1e-6f);

    float* o = out + (size_t)row * DIM + lane * 4;
#pragma unroll
    for (int i = 0; i < 6; ++i) {
        const int d = lane * 4 + i * 128;
        float4 g = *(const float4*)&gam[d];
        float4 be = *(const float4*)&bet[d];
        float4 r;
        r.x = (v[i].x - mu) * rstd * g.x + be.x;
        r.y = (v[i].y - mu) * rstd * g.y + be.y;
        r.z = (v[i].z - mu) * rstd * g.z + be.z;
        r.w = (v[i].w - mu) * rstd * g.w + be.w;
        *(float4*)(o + i * 128) = r;
        if (H16) {
            uint2 u = make_uint2(hpack(r.x, r.y), hpack(r.z, r.w));
            ((uint2*)out16)[((size_t)row * DIM + d) >> 2] = u;
        }
    }
}

// ---------------- launch ----------------
extern "C" void kernel_launch(void* const* d_in, const int* in_sizes, int n_in,
                              void* d_out, int out_size)
{
    const float* x    = (const float*)d_in[0];
    const int*   mask = (const int*)  d_in[1];
    const float* Wq   = (const float*)d_in[2];
    const float* bq   = (const float*)d_in[3];
    const float* Wk   = (const float*)d_in[4];
    const float* bk   = (const float*)d_in[5];
    const float* Wv   = (const float*)d_in[6];
    const float* bv   = (const float*)d_in[7];
    const float* Wo   = (const float*)d_in[8];
    const float* bo   = (const float*)d_in[9];
    const float* W1   = (const float*)d_in[10];
    const float* b1   = (const float*)d_in[11];
    const float* W2   = (const float*)d_in[12];
    const float* b2   = (const float*)d_in[13];
    const float* g1   = (const float*)d_in[14];
    const float* be1  = (const float*)d_in[15];
    const float* g2   = (const float*)d_in[16];
    const float* be2  = (const float*)d_in[17];
    float* out = (float*)d_out;

    __half *x16, *q16, *k16, *v16, *attn16, *h16, *ff16;
    unsigned *wq, *wk, *wv, *wo, *w1, *w2;
    float *t1, *h;
    cudaGetSymbolAddress((void**)&x16,    g_x16);
    cudaGetSymbolAddress((void**)&q16,    g_q16);
    cudaGetSymbolAddress((void**)&k16,    g_k16);
    cudaGetSymbolAddress((void**)&v16,    g_v16);
    cudaGetSymbolAddress((void**)&attn16, g_attn16);
    cudaGetSymbolAddress((void**)&h16,    g_h16);
    cudaGetSymbolAddress((void**)&ff16,   g_ff16);
    cudaGetSymbolAddress((void**)&wq,     g_wq);
    cudaGetSymbolAddress((void**)&wk,     g_wk);
    cudaGetSymbolAddress((void**)&wv,     g_wv);
    cudaGetSymbolAddress((void**)&wo,     g_wo);
    cudaGetSymbolAddress((void**)&w1,     g_w1);
    cudaGetSymbolAddress((void**)&w2,     g_w2);
    cudaGetSymbolAddress((void**)&t1,     g_t1);
    cudaGetSymbolAddress((void**)&h,      g_h);

    static bool attr_done = false;
    if (!attr_done) {
        cudaFuncSetAttribute(qkv16,        cudaFuncAttributeMaxDynamicSharedMemorySize, GS128);
        cudaFuncSetAttribute(tg<2,128,3>,  cudaFuncAttributeMaxDynamicSharedMemorySize, GS128);
        cudaFuncSetAttribute(tg<3,64,4>,   cudaFuncAttributeMaxDynamicSharedMemorySize, GS64);
        cudaFuncSetAttribute(attn_tc,      cudaFuncAttributeMaxDynamicSharedMemorySize, ATT_SMEM);
        attr_done = true;
    }

    // fused conversions / packing
    prep<<<PREP_BLOCKS, 256>>>(x, x16, Wq, Wk, Wv, Wo, wq, wk, wv, wo, W1, w1, W2, w2);

    // fused QKV -> fp16 [B,S,D]
    qkv16<<<dim3(18, ROWS / 128), 256, GS128>>>(x16, wq, wk, wv, bq, bk, bv, q16, k16, v16);

    // fp16 flash attention -> fp16 [B,S,D]
    attn_tc<<<BATCH * NH * (SEQ / 128), 256, ATT_SMEM>>>(q16, k16, v16, mask, attn16);

    // O projection + residual (fp32 out), LN1 (fp32 + fp16)
    tg<3,64,4><<<dim3(DIM / 128, ROWS / 64), 256, GS64>>>(attn16, wo, bo, x, t1, DIM, DIM);
    ln_kernel<1><<<ROWS / 8, 256>>>(t1, g1, be1, h, h16);

    // FFN
    tg<2,128,3><<<dim3(FFDIM / 128, ROWS / 128), 256, GS128>>>(h16, w1, b1, nullptr, ff16, FFDIM, DIM);
    tg<3,64,4><<<dim3(DIM / 128, ROWS / 64), 256, GS64>>>(ff16, w2, b2, h, t1, DIM, FFDIM);
    ln_kernel<0><<<ROWS / 8, 256>>>(t1, g2, be2, out, nullptr);
}

// round 16
// speedup vs baseline: 1.0803x; 1.0614x over previous
#include <cuda_runtime.h>
#include <cuda_fp16.h>
#include <math.h>
#include <stdint.h>

#define BATCH 4
#define SEQ   2048
#define DIM   768
#define NH    12
#define HDIM  64
#define FFDIM (4*DIM)
#define ROWS  (BATCH*SEQ)   /* 8192 */
#define RD    ((size_t)ROWS*DIM)

// ---------------- scratch (no cudaMalloc allowed) ----------------
__device__ __half   g_x16[(size_t)ROWS*DIM];
__device__ unsigned g_wq[(size_t)(DIM/2)*DIM];
__device__ unsigned g_wk[(size_t)(DIM/2)*DIM];
__device__ unsigned g_wv[(size_t)(DIM/2)*DIM];
__device__ unsigned g_wo[(size_t)(DIM/2)*DIM];
__device__ unsigned g_w1[(size_t)(DIM/2)*FFDIM];
__device__ unsigned g_w2[(size_t)(FFDIM/2)*DIM];
__device__ __half   g_q16[(size_t)ROWS*DIM];
__device__ __half   g_k16[(size_t)ROWS*DIM];
__device__ __half   g_v16[(size_t)ROWS*DIM];
__device__ __half   g_attn16[(size_t)ROWS*DIM];
__device__ __half   g_h16[(size_t)ROWS*DIM];
__device__ __half   g_ff16[(size_t)ROWS*FFDIM];
__device__ float    g_t1[2*(size_t)ROWS*DIM];   /* two split-K partials */
__device__ float    g_h[(size_t)ROWS*DIM];

// ---------------- helpers ----------------
__device__ __forceinline__ unsigned hpack(float lo, float hi) {
    unsigned r;
    asm("cvt.rn.f16x2.f32 %0, %1, %2;" : "=r"(r) : "f"(hi), "f"(lo));
    return r;
}
__device__ __forceinline__ uint32_t smem_u32(const void* p) {
    uint32_t a;
    asm("{ .reg .u64 t; cvta.to.shared.u64 t, %1; cvt.u32.u64 %0, t; }" : "=r"(a) : "l"(p));
    return a;
}
__device__ __forceinline__ void ldsm4(unsigned* d, uint32_t addr) {
    asm volatile("ldmatrix.sync.aligned.m8n8.x4.shared.b16 {%0,%1,%2,%3}, [%4];"
                 : "=r"(d[0]), "=r"(d[1]), "=r"(d[2]), "=r"(d[3]) : "r"(addr));
}
__device__ __forceinline__ void ldsm4t(unsigned* d, uint32_t addr) {
    asm volatile("ldmatrix.sync.aligned.m8n8.x4.trans.shared.b16 {%0,%1,%2,%3}, [%4];"
                 : "=r"(d[0]), "=r"(d[1]), "=r"(d[2]), "=r"(d[3]) : "r"(addr));
}
__device__ __forceinline__ void cpa16(uint32_t dst, const void* src) {
    asm volatile("cp.async.cg.shared.global [%0], [%1], 16;" :: "r"(dst), "l"(src));
}
#define CPA_COMMIT() asm volatile("cp.async.commit_group;" ::: "memory")
template<int N> __device__ __forceinline__ void cpa_wait() {
    asm volatile("cp.async.wait_group %0;" :: "n"(N) : "memory");
}

__device__ __forceinline__ void mma_fp16(float* d, const unsigned* a, const unsigned* b) {
    asm volatile(
        "mma.sync.aligned.m16n8k16.row.col.f32.f16.f16.f32 "
        "{%0,%1,%2,%3}, {%4,%5,%6,%7}, {%8,%9}, {%0,%1,%2,%3};\n"
        : "+f"(d[0]), "+f"(d[1]), "+f"(d[2]), "+f"(d[3])
        : "r"(a[0]), "r"(a[1]), "r"(a[2]), "r"(a[3]), "r"(b[0]), "r"(b[1]));
}

// ---------------- fused prep kernel (1D flattened tasks) ----------------
#define PREP_BLOCKS 9600

__global__ __launch_bounds__(256) void prep(const float* __restrict__ x, __half* __restrict__ x16,
                                            const float* __restrict__ Wq, const float* __restrict__ Wk,
                                            const float* __restrict__ Wv, const float* __restrict__ Wo,
                                            unsigned* oq, unsigned* ok, unsigned* ov, unsigned* oo,
                                            const float* __restrict__ W1, unsigned* o1,
                                            const float* __restrict__ W2, unsigned* o2)
{
    const int bid = blockIdx.x;
    const int tid = threadIdx.x;
    if (bid < 6144) {
        const size_t i = (size_t)bid * 256 + tid;
        float4 v = ((const float4*)x)[i];
        ((uint2*)x16)[i] = make_uint2(hpack(v.x, v.y), hpack(v.z, v.w));
        return;
    }
    const float* W; unsigned* O; int N; int idx;
    if (bid < 7296) {
        const int base = bid - 6144;
        const int z = base / 288;
        W = (z == 0) ? Wq : (z == 1) ? Wk : (z == 2) ? Wv : Wo;
        O = (z == 0) ? oq : (z == 1) ? ok : (z == 2) ? ov : oo;
        N = DIM;
        idx = (base % 288) * 256 + tid;
    } else if (bid < 8448) {
        W = W1; O = o1; N = FFDIM;
        idx = (bid - 7296) * 256 + tid;
    } else {
        W = W2; O = o2; N = DIM;
        idx = (bid - 8448) * 256 + tid;
    }
    const int kp = idx / (N / 4);
    const int nq = (idx % (N / 4)) * 4;
    float4 a = *(const float4*)&W[(size_t)(2 * kp) * N + nq];
    float4 b = *(const float4*)&W[(size_t)(2 * kp + 1) * N + nq];
    *(uint4*)&O[(size_t)kp * N + nq] =
        make_uint4(hpack(a.x, b.x), hpack(a.y, b.y), hpack(a.z, b.z), hpack(a.w, b.w));
}

// ======================================================================
// FP16 GEMM, cp.async pipeline. ALL shape params compile-time.
// MODE 1: plain fp16 out  2: gelu fp16  4: raw fp32 partial (split-K)
// LDA = A gmem row stride; K = loop depth.
// ======================================================================
#define SB2 136

template<int MODE, int BM, int STAGES, int N, int K, int LDA>
__device__ __forceinline__ void gemm_core(const __half* __restrict__ A,
                                          const unsigned* __restrict__ Bw,
                                          const float* __restrict__ bias,
                                          void* __restrict__ Cv,
                                          int bm, int bn, char* sm)
{
    constexpr int MT   = BM / 32;
    constexpr int ASTG = BM * 80;
    constexpr int BSTG = 16 * 544;
    constexpr int STG  = ASTG + BSTG;
    constexpr int NK   = K >> 5;

    const uint32_t sb = smem_u32(sm);
    const int tid  = threadIdx.x;
    const int lane = tid & 31;
    const int warp = tid >> 5;
    const int wr   = warp >> 2;
    const int wn   = warp & 3;
    const int r0   = lane >> 2;
    const int kq   = lane & 3;

    const uint32_t aoff = (uint32_t)(wr * (BM / 2) + (lane & 7) + ((lane >> 3) & 1) * 8) * 80u
                        + (uint32_t)((lane >> 4) & 1) * 16u;

    const int ar = (BM == 128) ? (tid >> 1) : (tid >> 2);
    const int ac = (BM == 128) ? ((tid & 1) * 2) : (tid & 3);
    const int br = tid >> 4;
    const int bc = (tid & 15) * 2;

    float acc[MT][4][4];
#pragma unroll
    for (int mt = 0; mt < MT; ++mt)
#pragma unroll
        for (int nt = 0; nt < 4; ++nt)
#pragma unroll
            for (int e = 0; e < 4; ++e) acc[mt][nt][e] = 0.f;

    auto sidx = [&](int t) -> int { return (STAGES == 4) ? (t & 3) : (t % 3); };

    auto issue = [&](int s, int t) {
        const __half* as = A + (size_t)(bm + ar) * LDA + t * 32 + ac * 8;
        uint32_t ad = sb + (uint32_t)(s * STG) + (uint32_t)(ar * 80 + ac * 16);
        cpa16(ad, as);
        if (BM == 128) cpa16(ad + 16, as + 8);
        const unsigned* bs = Bw + (size_t)(t * 16 + br) * N + bn + bc * 4;
        uint32_t bd = sb + (uint32_t)(s * STG + ASTG) + (uint32_t)(br * 544 + bc * 16);
        cpa16(bd, bs);
        cpa16(bd + 16, bs + 4);
    };

#pragma unroll
    for (int p = 0; p < STAGES - 1; ++p) { issue(p, p); CPA_COMMIT(); }

    for (int t = 0; t < NK; ++t) {
        if (STAGES == 3) {
            if (t + 1 < NK) cpa_wait<1>(); else cpa_wait<0>();
        } else {
            if (t + 2 < NK) cpa_wait<2>();
            else if (t + 1 < NK) cpa_wait<1>();
            else cpa_wait<0>();
        }
        __syncthreads();
        if (t + STAGES - 1 < NK) { issue(sidx(t + STAGES - 1), t + STAGES - 1); CPA_COMMIT(); }

        const unsigned* Bs = (const unsigned*)(sm + sidx(t) * STG + ASTG);
        const uint32_t a32 = sb + (uint32_t)(sidx(t) * STG) + aoff;
#pragma unroll
        for (int kc = 0; kc < 2; ++kc) {
            const int e = kc * 8 + kq;
            unsigned af[MT][4], bf[4][2];
#pragma unroll
            for (int mt = 0; mt < MT; ++mt)
                ldsm4(af[mt], a32 + (uint32_t)(mt * 16 * 80) + (uint32_t)(kc * 32));
#pragma unroll
            for (int nt = 0; nt < 4; ++nt) {
                const int n0 = wn * 32 + nt * 8 + r0;
                bf[nt][0] = Bs[e * SB2 + n0];
                bf[nt][1] = Bs[(e + 4) * SB2 + n0];
            }
#pragma unroll
            for (int mt = 0; mt < MT; ++mt)
#pragma unroll
                for (int nt = 0; nt < 4; ++nt)
                    mma_fp16(acc[mt][nt], af[mt], bf[nt]);
        }
    }

#pragma unroll
    for (int mt = 0; mt < MT; ++mt) {
        const int row_lo = bm + wr * (BM / 2) + mt * 16 + r0;
#pragma unroll
        for (int nt = 0; nt < 4; ++nt) {
            const int col = bn + wn * 32 + nt * 8 + kq * 2;
#pragma unroll
            for (int half_ = 0; half_ < 2; ++half_) {
                const int row = row_lo + half_ * 8;
                if (MODE == 4) {
                    *(float2*)&((float*)Cv)[(size_t)row * N + col] =
                        make_float2(acc[mt][nt][half_ * 2 + 0], acc[mt][nt][half_ * 2 + 1]);
                } else {
                    float vx = acc[mt][nt][half_ * 2 + 0] + bias[col];
                    float vy = acc[mt][nt][half_ * 2 + 1] + bias[col + 1];
                    if (MODE == 2) {
                        vx = 0.5f * vx * (1.f + erff(vx * 0.70710678118654752f));
                        vy = 0.5f * vy * (1.f + erff(vy * 0.70710678118654752f));
                    }
                    ((unsigned*)Cv)[((size_t)row * N + col) >> 1] = hpack(vx, vy);
                }
            }
        }
    }
}

#define GS128 (3 * (128*80 + 16*544))   /* 56832 */
#define GS64  (4 * ( 64*80 + 16*544))   /* 55296 */

// FFN1: gelu, fp16 out
__global__ __launch_bounds__(256) void ffn1_g(const __half* __restrict__ A,
                                              const unsigned* __restrict__ Bw,
                                              const float* __restrict__ bias,
                                              __half* __restrict__ C)
{
    extern __shared__ char smg[];
    gemm_core<2, 128, 3, FFDIM, DIM, DIM>(A, Bw, bias, C,
                                          blockIdx.y * 128, blockIdx.x * 128, smg);
}

// split-K GEMM: blockIdx.z selects K-half; raw fp32 partial out; N=DIM
template<int LDA>
__global__ __launch_bounds__(256) void tgsk(const __half* __restrict__ A,
                                            const unsigned* __restrict__ Bw,
                                            float* __restrict__ C)
{
    extern __shared__ char smg[];
    constexpr int HK = LDA / 2;
    const int z = blockIdx.z;
    gemm_core<4, 64, 4, DIM, HK, LDA>(A + (size_t)z * HK,
                                      Bw + (size_t)z * (LDA / 4) * DIM,
                                      nullptr,
                                      C + (size_t)z * RD,
                                      blockIdx.y * 64, blockIdx.x * 128, smg);
}

// fused QKV (outputs in natural [B,S,D] fp16): grid.x = 18
__global__ __launch_bounds__(256) void qkv16(const __half* __restrict__ A,
                                             const unsigned* __restrict__ wq,
                                             const unsigned* __restrict__ wk,
                                             const unsigned* __restrict__ wv,
                                             const float* __restrict__ bq,
                                             const float* __restrict__ bk,
                                             const float* __restrict__ bv,
                                             __half* q, __half* k, __half* v)
{
    extern __shared__ char smg[];
    const int sel = blockIdx.x / 6;
    const int bxl = blockIdx.x % 6;
    const unsigned* B = (sel == 0) ? wq : (sel == 1) ? wk : wv;
    const float* bias = (sel == 0) ? bq : (sel == 1) ? bk : bv;
    __half*      C    = (sel == 0) ? q  : (sel == 1) ? k  : v;
    gemm_core<1, 128, 3, DIM, DIM, DIM>(A, B, bias, C,
                                        blockIdx.y * 128, bxl * 128, smg);
}

// ======================================================================
// FP16 flash attention (R13/R15-proven): cp.async 3-stage, static-max
// h2exp2 softmax, P in registers, ldmatrix K (non-trans) + V (trans).
// ======================================================================
#define KSTG 9216
#define ATT_STG (2 * KSTG)
#define ATT_MB  (3 * ATT_STG)
#define ATT_SMEM (3 * ATT_STG + 4096)
#define CSCALE 0.18033688011112042f   /* 0.125 * log2(e) */

__global__ __launch_bounds__(256, 2) void attn_tc(const __half* __restrict__ q,
                                                  const __half* __restrict__ k,
                                                  const __half* __restrict__ v,
                                                  const int* __restrict__ mask,
                                                  __half* __restrict__ out)
{
    extern __shared__ char smc[];
    const uint32_t sb = smem_u32(smc);
    half2* mb2 = (half2*)(smc + ATT_MB);

    const int tid  = threadIdx.x;
    const int lane = tid & 31;
    const int warp = tid >> 5;

    const int qtile = blockIdx.x & 15;
    const int bh    = blockIdx.x >> 4;
    const int b     = bh / NH;
    const int h     = bh % NH;

    const int q0 = qtile * 128;

    const int r0 = lane >> 2;
    const int kq = lane & 3;

    const int kr  = tid & 63;
    const int kc2 = tid >> 6;

    const uint32_t koff = (uint32_t)((lane & 7) + ((lane >> 4) & 1) * 8) * 144u
                        + (uint32_t)((lane >> 3) & 1) * 16u;
    const uint32_t voff = (uint32_t)((lane & 7) + ((lane >> 3) & 1) * 8) * 144u
                        + (uint32_t)((lane >> 4) & 1) * 16u;

    for (int i = tid; i < SEQ / 2; i += 256) {
        int2 mv = ((const int2*)(mask + b * SEQ))[i];
        mb2[i] = __floats2half2_rn(mv.x ? 0.f : -1e30f, mv.y ? 0.f : -1e30f);
    }

    unsigned qa[4][4];
    {
        const __half* qp = q + (size_t)(b * SEQ + q0 + warp * 16) * DIM + h * HDIM;
#pragma unroll
        for (int kc = 0; kc < 4; ++kc) {
            const int c0 = kc * 16 + kq * 2;
            qa[kc][0] = *(const unsigned*)(qp + (size_t)r0 * DIM + c0);
            qa[kc][1] = *(const unsigned*)(qp + (size_t)(r0 + 8) * DIM + c0);
            qa[kc][2] = *(const unsigned*)(qp + (size_t)r0 * DIM + c0 + 8);
            qa[kc][3] = *(const unsigned*)(qp + (size_t)(r0 + 8) * DIM + c0 + 8);
        }
    }

    float ls0 = 0.f, ls1 = 0.f;
    float oacc[8][4];
#pragma unroll
    for (int nt = 0; nt < 8; ++nt)
#pragma unroll
        for (int e = 0; e < 4; ++e) oacc[nt][e] = 0.f;

    auto issue = [&](int s, int kt) {
        const __half* ks = k + (size_t)(b * SEQ + kt * 64 + kr) * DIM + h * HDIM + kc2 * 16;
        uint32_t kd = sb + (uint32_t)(s * ATT_STG) + (uint32_t)(kr * 144 + kc2 * 32);
        cpa16(kd, ks);
        cpa16(kd + 16, ks + 8);
        const __half* vs = v + (size_t)(b * SEQ + kt * 64 + kr) * DIM + h * HDIM + kc2 * 16;
        uint32_t vd = kd + KSTG;
        cpa16(vd, vs);
        cpa16(vd + 16, vs + 8);
    };

    const int NT = SEQ / 64;   // 32
    issue(0, 0); CPA_COMMIT();
    issue(1, 1); CPA_COMMIT();

    for (int kt = 0; kt < NT; ++kt) {
        if (kt + 1 < NT) { cpa_wait<1>(); } else { cpa_wait<0>(); }
        __syncthreads();
        if (kt + 2 < NT) { issue((kt + 2) % 3, kt + 2); CPA_COMMIT(); }

        const uint32_t kb = sb + (uint32_t)((kt % 3) * ATT_STG);
        const uint32_t vb = kb + KSTG;

        float sf[8][4];
#pragma unroll
        for (int nt = 0; nt < 8; ++nt)
#pragma unroll
            for (int e = 0; e < 4; ++e) sf[nt][e] = 0.f;

#pragma unroll
        for (int np = 0; np < 4; ++np) {
#pragma unroll
            for (int kc = 0; kc < 4; ++kc) {
                unsigned b4[4];
                ldsm4(b4, kb + koff + (uint32_t)(np * 2304) + (uint32_t)(kc * 32));
                mma_fp16(sf[2 * np],     qa[kc], b4);
                mma_fp16(sf[2 * np + 1], qa[kc], b4 + 2);
            }
        }

        const half2* mt = mb2 + kt * 32;
        unsigned pa[4][4];
        half2 l2a = __floats2half2_rn(0.f, 0.f);
        half2 l2b = l2a;
#pragma unroll
        for (int kc = 0; kc < 4; ++kc) {
#pragma unroll
            for (int j = 0; j < 2; ++j) {
                const int nt = 2 * kc + j;
                const half2 bias = mt[nt * 4 + kq];
                half2 p0 = h2exp2(__hadd2(
                    __floats2half2_rn(sf[nt][0] * CSCALE, sf[nt][1] * CSCALE), bias));
                half2 p1 = h2exp2(__hadd2(
                    __floats2half2_rn(sf[nt][2] * CSCALE, sf[nt][3] * CSCALE), bias));
                pa[kc][2 * j]     = *(unsigned*)&p0;
                pa[kc][2 * j + 1] = *(unsigned*)&p1;
                l2a = __hadd2(l2a, p0);
                l2b = __hadd2(l2b, p1);
            }
        }
        {
            float2 fa = __half22float2(l2a), fb = __half22float2(l2b);
            ls0 += fa.x + fa.y;
            ls1 += fb.x + fb.y;
        }

#pragma unroll
        for (int ntA = 0; ntA < 8; ntA += 2) {
#pragma unroll
            for (int kc = 0; kc < 4; ++kc) {
                unsigned v4[4];
                ldsm4t(v4, vb + voff + (uint32_t)(kc * 16 * 144) + (uint32_t)(ntA * 16));
                mma_fp16(oacc[ntA],     pa[kc], v4);
                mma_fp16(oacc[ntA + 1], pa[kc], v4 + 2);
            }
        }
    }

    ls0 += __shfl_xor_sync(0xffffffffu, ls0, 1);
    ls0 += __shfl_xor_sync(0xffffffffu, ls0, 2);
    ls1 += __shfl_xor_sync(0xffffffffu, ls1, 1);
    ls1 += __shfl_xor_sync(0xffffffffu, ls1, 2);
    const float inv0 = 1.f / ls0;
    const float inv1 = 1.f / ls1;
    const int row_g = q0 + warp * 16 + r0;
    unsigned* o32 = (unsigned*)out;
#pragma unroll
    for (int nt = 0; nt < 8; ++nt) {
        const int col = h * HDIM + nt * 8 + kq * 2;
        o32[((size_t)(b * SEQ + row_g) * DIM + col) >> 1] =
            hpack(oacc[nt][0] * inv0, oacc[nt][1] * inv0);
        o32[((size_t)(b * SEQ + row_g + 8) * DIM + col) >> 1] =
            hpack(oacc[nt][2] * inv1, oacc[nt][3] * inv1);
    }
}

// ---------------- fused LayerNorm: in = p0 + p1 + res + bias ----------------
template<int H16>
__global__ __launch_bounds__(256) void ln_fuse(const float* __restrict__ p0,
                                               const float* __restrict__ p1,
                                               const float* __restrict__ res,
                                               const float* __restrict__ bias,
                                               const float* __restrict__ gam,
                                               const float* __restrict__ bet,
                                               float* __restrict__ out,
                                               __half* __restrict__ out16)
{
    const int warp = threadIdx.x >> 5;
    const int lane = threadIdx.x & 31;
    const int row  = blockIdx.x * 8 + warp;
    const size_t rb = (size_t)row * DIM;

    float4 v[6];
    float s = 0.f, s2 = 0.f;
#pragma unroll
    for (int i = 0; i < 6; ++i) {
        const int d = lane * 4 + i * 128;
        float4 a = *(const float4*)&p0[rb + d];
        float4 b = *(const float4*)&p1[rb + d];
        float4 r = *(const float4*)&res[rb + d];
        float4 bi = *(const float4*)&bias[d];
        v[i].x = a.x + b.x + r.x + bi.x;
        v[i].y = a.y + b.y + r.y + bi.y;
        v[i].z = a.z + b.z + r.z + bi.z;
        v[i].w = a.w + b.w + r.w + bi.w;
        s  += v[i].x + v[i].y + v[i].z + v[i].w;
        s2 += v[i].x * v[i].x + v[i].y * v[i].y + v[i].z * v[i].z + v[i].w * v[i].w;
    }
#pragma unroll
    for (int o = 16; o > 0; o >>= 1) {
        s  += __shfl_xor_sync(0xffffffffu, s,  o);
        s2 += __shfl_xor_sync(0xffffffffu, s2, o);
    }
    const float mu   = s * (1.f / DIM);
    const float rstd = rsqrtf(s2 * (1.f / DIM) - mu * mu + 1e-6f);

#pragma unroll
    for (int i = 0; i < 6; ++i) {
        const int d = lane * 4 + i * 128;
        float4 g = *(const float4*)&gam[d];
        float4 be = *(const float4*)&bet[d];
        float4 r;
        r.x = (v[i].x - mu) * rstd * g.x + be.x;
        r.y = (v[i].y - mu) * rstd * g.y + be.y;
        r.z = (v[i].z - mu) * rstd * g.z + be.z;
        r.w = (v[i].w - mu) * rstd * g.w + be.w;
        *(float4*)&out[rb + d] = r;
        if (H16) {
            uint2 u = make_uint2(hpack(r.x, r.y), hpack(r.z, r.w));
            ((uint2*)out16)[(rb + d) >> 2] = u;
        }
    }
}

// ---------------- launch ----------------
extern "C" void kernel_launch(void* const* d_in, const int* in_sizes, int n_in,
                              void* d_out, int out_size)
{
    const float* x    = (const float*)d_in[0];
    const int*   mask = (const int*)  d_in[1];
    const float* Wq   = (const float*)d_in[2];
    const float* bq   = (const float*)d_in[3];
    const float* Wk   = (const float*)d_in[4];
    const float* bk   = (const float*)d_in[5];
    const float* Wv   = (const float*)d_in[6];
    const float* bv   = (const float*)d_in[7];
    const float* Wo   = (const float*)d_in[8];
    const float* bo   = (const float*)d_in[9];
    const float* W1   = (const float*)d_in[10];
    const float* b1   = (const float*)d_in[11];
    const float* W2   = (const float*)d_in[12];
    const float* b2   = (const float*)d_in[13];
    const float* g1   = (const float*)d_in[14];
    const float* be1  = (const float*)d_in[15];
    const float* g2   = (const float*)d_in[16];
    const float* be2  = (const float*)d_in[17];
    float* out = (float*)d_out;

    __half *x16, *q16, *k16, *v16, *attn16, *h16, *ff16;
    unsigned *wq, *wk, *wv, *wo, *w1, *w2;
    float *t1, *h;
    cudaGetSymbolAddress((void**)&x16,    g_x16);
    cudaGetSymbolAddress((void**)&q16,    g_q16);
    cudaGetSymbolAddress((void**)&k16,    g_k16);
    cudaGetSymbolAddress((void**)&v16,    g_v16);
    cudaGetSymbolAddress((void**)&attn16, g_attn16);
    cudaGetSymbolAddress((void**)&h16,    g_h16);
    cudaGetSymbolAddress((void**)&ff16,   g_ff16);
    cudaGetSymbolAddress((void**)&wq,     g_wq);
    cudaGetSymbolAddress((void**)&wk,     g_wk);
    cudaGetSymbolAddress((void**)&wv,     g_wv);
    cudaGetSymbolAddress((void**)&wo,     g_wo);
    cudaGetSymbolAddress((void**)&w1,     g_w1);
    cudaGetSymbolAddress((void**)&w2,     g_w2);
    cudaGetSymbolAddress((void**)&t1,     g_t1);
    cudaGetSymbolAddress((void**)&h,      g_h);

    static bool attr_done = false;
    if (!attr_done) {
        cudaFuncSetAttribute(qkv16,       cudaFuncAttributeMaxDynamicSharedMemorySize, GS128);
        cudaFuncSetAttribute(ffn1_g,      cudaFuncAttributeMaxDynamicSharedMemorySize, GS128);
        cudaFuncSetAttribute(tgsk<DIM>,   cudaFuncAttributeMaxDynamicSharedMemorySize, GS64);
        cudaFuncSetAttribute(tgsk<FFDIM>, cudaFuncAttributeMaxDynamicSharedMemorySize, GS64);
        cudaFuncSetAttribute(attn_tc,     cudaFuncAttributeMaxDynamicSharedMemorySize, ATT_SMEM);
        attr_done = true;
    }

    // fused conversions / packing
    prep<<<PREP_BLOCKS, 256>>>(x, x16, Wq, Wk, Wv, Wo, wq, wk, wv, wo, W1, w1, W2, w2);

    // fused QKV -> fp16 [B,S,D]
    qkv16<<<dim3(18, ROWS / 128), 256, GS128>>>(x16, wq, wk, wv, bq, bk, bv, q16, k16, v16);

    // fp16 flash attention -> fp16 [B,S,D]
    attn_tc<<<BATCH * NH * (SEQ / 128), 256, ATT_SMEM>>>(q16, k16, v16, mask, attn16);

    // O projection split-K (partials), LN1 fused add (p0+p1+x+bo)
    tgsk<DIM><<<dim3(DIM / 128, ROWS / 64, 2), 256, GS64>>>(attn16, wo, t1);
    ln_fuse<1><<<ROWS / 8, 256>>>(t1, t1 + RD, x, bo, g1, be1, h, h16);

    // FFN1 (gelu, fp16 out)
    ffn1_g<<<dim3(FFDIM / 128, ROWS / 128), 256, GS128>>>(h16, w1, b1, ff16);

    // FFN2 split-K (partials), LN2 fused add (p0+p1+h+b2)
    tgsk<FFDIM><<<dim3(DIM / 128, ROWS / 64, 2), 256, GS64>>>(ff16, w2, t1);
    ln_fuse<0><<<ROWS / 8, 256>>>(t1, t1 + RD, h, b2, g2, be2, out, nullptr);
}

// round 17
// speedup vs baseline: 1.0898x; 1.0088x over previous
#include <cuda_runtime.h>
#include <cuda_fp16.h>
#include <math.h>
#include <stdint.h>

#define BATCH 4
#define SEQ   2048
#define DIM   768
#define NH    12
#define HDIM  64
#define FFDIM (4*DIM)
#define ROWS  (BATCH*SEQ)   /* 8192 */
#define RD    ((size_t)ROWS*DIM)

// ---------------- scratch (no cudaMalloc allowed) ----------------
__device__ __half   g_x16[(size_t)ROWS*DIM];
__device__ unsigned g_wq[(size_t)(DIM/2)*DIM];
__device__ unsigned g_wk[(size_t)(DIM/2)*DIM];
__device__ unsigned g_wv[(size_t)(DIM/2)*DIM];
__device__ unsigned g_wo[(size_t)(DIM/2)*DIM];
__device__ unsigned g_w1[(size_t)(DIM/2)*FFDIM];
__device__ unsigned g_w2[(size_t)(FFDIM/2)*DIM];
__device__ __half   g_q16[(size_t)ROWS*DIM];
__device__ __half   g_k16[(size_t)ROWS*DIM];
__device__ __half   g_v16[(size_t)ROWS*DIM];
__device__ __half   g_attn16[(size_t)ROWS*DIM];
__device__ __half   g_h16[(size_t)ROWS*DIM];
__device__ __half   g_ff16[(size_t)ROWS*FFDIM];
__device__ float    g_t1[2*(size_t)ROWS*DIM];   /* two split-K partials */
__device__ float    g_h[(size_t)ROWS*DIM];

// ---------------- helpers ----------------
__device__ __forceinline__ unsigned hpack(float lo, float hi) {
    unsigned r;
    asm("cvt.rn.f16x2.f32 %0, %1, %2;" : "=r"(r) : "f"(hi), "f"(lo));
    return r;
}
__device__ __forceinline__ uint32_t smem_u32(const void* p) {
    uint32_t a;
    asm("{ .reg .u64 t; cvta.to.shared.u64 t, %1; cvt.u32.u64 %0, t; }" : "=r"(a) : "l"(p));
    return a;
}
__device__ __forceinline__ void ldsm4(unsigned* d, uint32_t addr) {
    asm volatile("ldmatrix.sync.aligned.m8n8.x4.shared.b16 {%0,%1,%2,%3}, [%4];"
                 : "=r"(d[0]), "=r"(d[1]), "=r"(d[2]), "=r"(d[3]) : "r"(addr));
}
__device__ __forceinline__ void ldsm4t(unsigned* d, uint32_t addr) {
    asm volatile("ldmatrix.sync.aligned.m8n8.x4.trans.shared.b16 {%0,%1,%2,%3}, [%4];"
                 : "=r"(d[0]), "=r"(d[1]), "=r"(d[2]), "=r"(d[3]) : "r"(addr));
}
__device__ __forceinline__ void cpa16(uint32_t dst, const void* src) {
    asm volatile("cp.async.cg.shared.global [%0], [%1], 16;" :: "r"(dst), "l"(src));
}
#define CPA_COMMIT() asm volatile("cp.async.commit_group;" ::: "memory")
template<int N> __device__ __forceinline__ void cpa_wait() {
    asm volatile("cp.async.wait_group %0;" :: "n"(N) : "memory");
}

__device__ __forceinline__ void mma_fp16(float* d, const unsigned* a, const unsigned* b) {
    asm volatile(
        "mma.sync.aligned.m16n8k16.row.col.f32.f16.f16.f32 "
        "{%0,%1,%2,%3}, {%4,%5,%6,%7}, {%8,%9}, {%0,%1,%2,%3};\n"
        : "+f"(d[0]), "+f"(d[1]), "+f"(d[2]), "+f"(d[3])
        : "r"(a[0]), "r"(a[1]), "r"(a[2]), "r"(a[3]), "r"(b[0]), "r"(b[1]));
}

// ---------------- fused prep kernel (1D flattened tasks) ----------------
#define PREP_BLOCKS 9600

__global__ __launch_bounds__(256) void prep(const float* __restrict__ x, __half* __restrict__ x16,
                                            const float* __restrict__ Wq, const float* __restrict__ Wk,
                                            const float* __restrict__ Wv, const float* __restrict__ Wo,
                                            unsigned* oq, unsigned* ok, unsigned* ov, unsigned* oo,
                                            const float* __restrict__ W1, unsigned* o1,
                                            const float* __restrict__ W2, unsigned* o2)
{
    const int bid = blockIdx.x;
    const int tid = threadIdx.x;
    if (bid < 6144) {
        const size_t i = (size_t)bid * 256 + tid;
        float4 v = ((const float4*)x)[i];
        ((uint2*)x16)[i] = make_uint2(hpack(v.x, v.y), hpack(v.z, v.w));
        return;
    }
    const float* W; unsigned* O; int N; int idx;
    if (bid < 7296) {
        const int base = bid - 6144;
        const int z = base / 288;
        W = (z == 0) ? Wq : (z == 1) ? Wk : (z == 2) ? Wv : Wo;
        O = (z == 0) ? oq : (z == 1) ? ok : (z == 2) ? ov : oo;
        N = DIM;
        idx = (base % 288) * 256 + tid;
    } else if (bid < 8448) {
        W = W1; O = o1; N = FFDIM;
        idx = (bid - 7296) * 256 + tid;
    } else {
        W = W2; O = o2; N = DIM;
        idx = (bid - 8448) * 256 + tid;
    }
    const int kp = idx / (N / 4);
    const int nq = (idx % (N / 4)) * 4;
    float4 a = *(const float4*)&W[(size_t)(2 * kp) * N + nq];
    float4 b = *(const float4*)&W[(size_t)(2 * kp + 1) * N + nq];
    *(uint4*)&O[(size_t)kp * N + nq] =
        make_uint4(hpack(a.x, b.x), hpack(a.y, b.y), hpack(a.z, b.z), hpack(a.w, b.w));
}

// ======================================================================
// FP16 GEMM, cp.async pipeline. ALL shape params compile-time.
// MODE 1: plain fp16 out  2: gelu fp16  4: raw fp32 partial (split-K)
// ======================================================================
#define SB2 136

template<int MODE, int BM, int STAGES, int N, int K, int LDA>
__device__ __forceinline__ void gemm_core(const __half* __restrict__ A,
                                          const unsigned* __restrict__ Bw,
                                          const float* __restrict__ bias,
                                          void* __restrict__ Cv,
                                          int bm, int bn, char* sm)
{
    constexpr int MT   = BM / 32;
    constexpr int ASTG = BM * 80;
    constexpr int BSTG = 16 * 544;
    constexpr int STG  = ASTG + BSTG;
    constexpr int NK   = K >> 5;

    const uint32_t sb = smem_u32(sm);
    const int tid  = threadIdx.x;
    const int lane = tid & 31;
    const int warp = tid >> 5;
    const int wr   = warp >> 2;
    const int wn   = warp & 3;
    const int r0   = lane >> 2;
    const int kq   = lane & 3;

    const uint32_t aoff = (uint32_t)(wr * (BM / 2) + (lane & 7) + ((lane >> 3) & 1) * 8) * 80u
                        + (uint32_t)((lane >> 4) & 1) * 16u;

    const int ar = (BM == 128) ? (tid >> 1) : (tid >> 2);
    const int ac = (BM == 128) ? ((tid & 1) * 2) : (tid & 3);
    const int br = tid >> 4;
    const int bc = (tid & 15) * 2;

    float acc[MT][4][4];
#pragma unroll
    for (int mt = 0; mt < MT; ++mt)
#pragma unroll
        for (int nt = 0; nt < 4; ++nt)
#pragma unroll
            for (int e = 0; e < 4; ++e) acc[mt][nt][e] = 0.f;

    auto sidx = [&](int t) -> int { return (STAGES == 4) ? (t & 3) : (t % 3); };

    auto issue = [&](int s, int t) {
        const __half* as = A + (size_t)(bm + ar) * LDA + t * 32 + ac * 8;
        uint32_t ad = sb + (uint32_t)(s * STG) + (uint32_t)(ar * 80 + ac * 16);
        cpa16(ad, as);
        if (BM == 128) cpa16(ad + 16, as + 8);
        const unsigned* bs = Bw + (size_t)(t * 16 + br) * N + bn + bc * 4;
        uint32_t bd = sb + (uint32_t)(s * STG + ASTG) + (uint32_t)(br * 544 + bc * 16);
        cpa16(bd, bs);
        cpa16(bd + 16, bs + 4);
    };

#pragma unroll
    for (int p = 0; p < STAGES - 1; ++p) { issue(p, p); CPA_COMMIT(); }

    for (int t = 0; t < NK; ++t) {
        if (STAGES == 3) {
            if (t + 1 < NK) cpa_wait<1>(); else cpa_wait<0>();
        } else {
            if (t + 2 < NK) cpa_wait<2>();
            else if (t + 1 < NK) cpa_wait<1>();
            else cpa_wait<0>();
        }
        __syncthreads();
        if (t + STAGES - 1 < NK) { issue(sidx(t + STAGES - 1), t + STAGES - 1); CPA_COMMIT(); }

        const unsigned* Bs = (const unsigned*)(sm + sidx(t) * STG + ASTG);
        const uint32_t a32 = sb + (uint32_t)(sidx(t) * STG) + aoff;
#pragma unroll
        for (int kc = 0; kc < 2; ++kc) {
            const int e = kc * 8 + kq;
            unsigned af[MT][4], bf[4][2];
#pragma unroll
            for (int mt = 0; mt < MT; ++mt)
                ldsm4(af[mt], a32 + (uint32_t)(mt * 16 * 80) + (uint32_t)(kc * 32));
#pragma unroll
            for (int nt = 0; nt < 4; ++nt) {
                const int n0 = wn * 32 + nt * 8 + r0;
                bf[nt][0] = Bs[e * SB2 + n0];
                bf[nt][1] = Bs[(e + 4) * SB2 + n0];
            }
#pragma unroll
            for (int mt = 0; mt < MT; ++mt)
#pragma unroll
                for (int nt = 0; nt < 4; ++nt)
                    mma_fp16(acc[mt][nt], af[mt], bf[nt]);
        }
    }

#pragma unroll
    for (int mt = 0; mt < MT; ++mt) {
        const int row_lo = bm + wr * (BM / 2) + mt * 16 + r0;
#pragma unroll
        for (int nt = 0; nt < 4; ++nt) {
            const int col = bn + wn * 32 + nt * 8 + kq * 2;
#pragma unroll
            for (int half_ = 0; half_ < 2; ++half_) {
                const int row = row_lo + half_ * 8;
                if (MODE == 4) {
                    *(float2*)&((float*)Cv)[(size_t)row * N + col] =
                        make_float2(acc[mt][nt][half_ * 2 + 0], acc[mt][nt][half_ * 2 + 1]);
                } else {
                    float vx = acc[mt][nt][half_ * 2 + 0] + bias[col];
                    float vy = acc[mt][nt][half_ * 2 + 1] + bias[col + 1];
                    if (MODE == 2) {
                        vx = 0.5f * vx * (1.f + erff(vx * 0.70710678118654752f));
                        vy = 0.5f * vy * (1.f + erff(vy * 0.70710678118654752f));
                    }
                    ((unsigned*)Cv)[((size_t)row * N + col) >> 1] = hpack(vx, vy);
                }
            }
        }
    }
}

#define GS64  (4 * ( 64*80 + 16*544))   /* 55296 */

// FFN1: gelu, fp16 out — BM=64, 4-stage
__global__ __launch_bounds__(256) void ffn1_g(const __half* __restrict__ A,
                                              const unsigned* __restrict__ Bw,
                                              const float* __restrict__ bias,
                                              __half* __restrict__ C)
{
    extern __shared__ char smg[];
    gemm_core<2, 64, 4, FFDIM, DIM, DIM>(A, Bw, bias, C,
                                         blockIdx.y * 64, blockIdx.x * 128, smg);
}

// split-K GEMM: blockIdx.z selects K-half; raw fp32 partial out; N=DIM
template<int LDA>
__global__ __launch_bounds__(256) void tgsk(const __half* __restrict__ A,
                                            const unsigned* __restrict__ Bw,
                                            float* __restrict__ C)
{
    extern __shared__ char smg[];
    constexpr int HK = LDA / 2;
    const int z = blockIdx.z;
    gemm_core<4, 64, 4, DIM, HK, LDA>(A + (size_t)z * HK,
                                      Bw + (size_t)z * (LDA / 4) * DIM,
                                      nullptr,
                                      C + (size_t)z * RD,
                                      blockIdx.y * 64, blockIdx.x * 128, smg);
}

// fused QKV (fp16 [B,S,D] out) — BM=64, 4-stage; grid.x = 18
__global__ __launch_bounds__(256) void qkv16(const __half* __restrict__ A,
                                             const unsigned* __restrict__ wq,
                                             const unsigned* __restrict__ wk,
                                             const unsigned* __restrict__ wv,
                                             const float* __restrict__ bq,
                                             const float* __restrict__ bk,
                                             const float* __restrict__ bv,
                                             __half* q, __half* k, __half* v)
{
    extern __shared__ char smg[];
    const int sel = blockIdx.x / 6;
    const int bxl = blockIdx.x % 6;
    const unsigned* B = (sel == 0) ? wq : (sel == 1) ? wk : wv;
    const float* bias = (sel == 0) ? bq : (sel == 1) ? bk : bv;
    __half*      C    = (sel == 0) ? q  : (sel == 1) ? k  : v;
    gemm_core<1, 64, 4, DIM, DIM, DIM>(A, B, bias, C,
                                       blockIdx.y * 64, bxl * 128, smg);
}

// ======================================================================
// FP16 flash attention (R13/R16-proven): cp.async 3-stage, static-max
// h2exp2 softmax, P in registers, ldmatrix K (non-trans) + V (trans).
// ======================================================================
#define KSTG 9216
#define ATT_STG (2 * KSTG)
#define ATT_MB  (3 * ATT_STG)
#define ATT_SMEM (3 * ATT_STG + 4096)
#define CSCALE 0.18033688011112042f   /* 0.125 * log2(e) */

__global__ __launch_bounds__(256, 2) void attn_tc(const __half* __restrict__ q,
                                                  const __half* __restrict__ k,
                                                  const __half* __restrict__ v,
                                                  const int* __restrict__ mask,
                                                  __half* __restrict__ out)
{
    extern __shared__ char smc[];
    const uint32_t sb = smem_u32(smc);
    half2* mb2 = (half2*)(smc + ATT_MB);

    const int tid  = threadIdx.x;
    const int lane = tid & 31;
    const int warp = tid >> 5;

    const int qtile = blockIdx.x & 15;
    const int bh    = blockIdx.x >> 4;
    const int b     = bh / NH;
    const int h     = bh % NH;

    const int q0 = qtile * 128;

    const int r0 = lane >> 2;
    const int kq = lane & 3;

    const int kr  = tid & 63;
    const int kc2 = tid >> 6;

    const uint32_t koff = (uint32_t)((lane & 7) + ((lane >> 4) & 1) * 8) * 144u
                        + (uint32_t)((lane >> 3) & 1) * 16u;
    const uint32_t voff = (uint32_t)((lane & 7) + ((lane >> 3) & 1) * 8) * 144u
                        + (uint32_t)((lane >> 4) & 1) * 16u;

    for (int i = tid; i < SEQ / 2; i += 256) {
        int2 mv = ((const int2*)(mask + b * SEQ))[i];
        mb2[i] = __floats2half2_rn(mv.x ? 0.f : -1e30f, mv.y ? 0.f : -1e30f);
    }

    unsigned qa[4][4];
    {
        const __half* qp = q + (size_t)(b * SEQ + q0 + warp * 16) * DIM + h * HDIM;
#pragma unroll
        for (int kc = 0; kc < 4; ++kc) {
            const int c0 = kc * 16 + kq * 2;
            qa[kc][0] = *(const unsigned*)(qp + (size_t)r0 * DIM + c0);
            qa[kc][1] = *(const unsigned*)(qp + (size_t)(r0 + 8) * DIM + c0);
            qa[kc][2] = *(const unsigned*)(qp + (size_t)r0 * DIM + c0 + 8);
            qa[kc][3] = *(const unsigned*)(qp + (size_t)(r0 + 8) * DIM + c0 + 8);
        }
    }

    float ls0 = 0.f, ls1 = 0.f;
    float oacc[8][4];
#pragma unroll
    for (int nt = 0; nt < 8; ++nt)
#pragma unroll
        for (int e = 0; e < 4; ++e) oacc[nt][e] = 0.f;

    auto issue = [&](int s, int kt) {
        const __half* ks = k + (size_t)(b * SEQ + kt * 64 + kr) * DIM + h * HDIM + kc2 * 16;
        uint32_t kd = sb + (uint32_t)(s * ATT_STG) + (uint32_t)(kr * 144 + kc2 * 32);
        cpa16(kd, ks);
        cpa16(kd + 16, ks + 8);
        const __half* vs = v + (size_t)(b * SEQ + kt * 64 + kr) * DIM + h * HDIM + kc2 * 16;
        uint32_t vd = kd + KSTG;
        cpa16(vd, vs);
        cpa16(vd + 16, vs + 8);
    };

    const int NT = SEQ / 64;   // 32
    issue(0, 0); CPA_COMMIT();
    issue(1, 1); CPA_COMMIT();

    for (int kt = 0; kt < NT; ++kt) {
        if (kt + 1 < NT) { cpa_wait<1>(); } else { cpa_wait<0>(); }
        __syncthreads();
        if (kt + 2 < NT) { issue((kt + 2) % 3, kt + 2); CPA_COMMIT(); }

        const uint32_t kb = sb + (uint32_t)((kt % 3) * ATT_STG);
        const uint32_t vb = kb + KSTG;

        float sf[8][4];
#pragma unroll
        for (int nt = 0; nt < 8; ++nt)
#pragma unroll
            for (int e = 0; e < 4; ++e) sf[nt][e] = 0.f;

#pragma unroll
        for (int np = 0; np < 4; ++np) {
#pragma unroll
            for (int kc = 0; kc < 4; ++kc) {
                unsigned b4[4];
                ldsm4(b4, kb + koff + (uint32_t)(np * 2304) + (uint32_t)(kc * 32));
                mma_fp16(sf[2 * np],     qa[kc], b4);
                mma_fp16(sf[2 * np + 1], qa[kc], b4 + 2);
            }
        }

        const half2* mt = mb2 + kt * 32;
        unsigned pa[4][4];
        half2 l2a = __floats2half2_rn(0.f, 0.f);
        half2 l2b = l2a;
#pragma unroll
        for (int kc = 0; kc < 4; ++kc) {
#pragma unroll
            for (int j = 0; j < 2; ++j) {
                const int nt = 2 * kc + j;
                const half2 bias = mt[nt * 4 + kq];
                half2 p0 = h2exp2(__hadd2(
                    __floats2half2_rn(sf[nt][0] * CSCALE, sf[nt][1] * CSCALE), bias));
                half2 p1 = h2exp2(__hadd2(
                    __floats2half2_rn(sf[nt][2] * CSCALE, sf[nt][3] * CSCALE), bias));
                pa[kc][2 * j]     = *(unsigned*)&p0;
                pa[kc][2 * j + 1] = *(unsigned*)&p1;
                l2a = __hadd2(l2a, p0);
                l2b = __hadd2(l2b, p1);
            }
        }
        {
            float2 fa = __half22float2(l2a), fb = __half22float2(l2b);
            ls0 += fa.x + fa.y;
            ls1 += fb.x + fb.y;
        }

#pragma unroll
        for (int ntA = 0; ntA < 8; ntA += 2) {
#pragma unroll
            for (int kc = 0; kc < 4; ++kc) {
                unsigned v4[4];
                ldsm4t(v4, vb + voff + (uint32_t)(kc * 16 * 144) + (uint32_t)(ntA * 16));
                mma_fp16(oacc[ntA],     pa[kc], v4);
                mma_fp16(oacc[ntA + 1], pa[kc], v4 + 2);
            }
        }
    }

    ls0 += __shfl_xor_sync(0xffffffffu, ls0, 1);
    ls0 += __shfl_xor_sync(0xffffffffu, ls0, 2);
    ls1 += __shfl_xor_sync(0xffffffffu, ls1, 1);
    ls1 += __shfl_xor_sync(0xffffffffu, ls1, 2);
    const float inv0 = 1.f / ls0;
    const float inv1 = 1.f / ls1;
    const int row_g = q0 + warp * 16 + r0;
    unsigned* o32 = (unsigned*)out;
#pragma unroll
    for (int nt = 0; nt < 8; ++nt) {
        const int col = h * HDIM + nt * 8 + kq * 2;
        o32[((size_t)(b * SEQ + row_g) * DIM + col) >> 1] =
            hpack(oacc[nt][0] * inv0, oacc[nt][1] * inv0);
        o32[((size_t)(b * SEQ + row_g + 8) * DIM + col) >> 1] =
            hpack(oacc[nt][2] * inv1, oacc[nt][3] * inv1);
    }
}

// ---------------- fused LayerNorm: in = p0 + p1 + res + bias ----------------
template<int H16>
__global__ __launch_bounds__(256) void ln_fuse(const float* __restrict__ p0,
                                               const float* __restrict__ p1,
                                               const float* __restrict__ res,
                                               const float* __restrict__ bias,
                                               const float* __restrict__ gam,
                                               const float* __restrict__ bet,
                                               float* __restrict__ out,
                                               __half* __restrict__ out16)
{
    const int warp = threadIdx.x >> 5;
    const int lane = threadIdx.x & 31;
    const int row  = blockIdx.x * 8 + warp;
    const size_t rb = (size_t)row * DIM;

    float4 v[6];
    float s = 0.f, s2 = 0.f;
#pragma unroll
    for (int i = 0; i < 6; ++i) {
        const int d = lane * 4 + i * 128;
        float4 a = *(const float4*)&p0[rb + d];
        float4 b = *(const float4*)&p1[rb + d];
        float4 r = *(const float4*)&res[rb + d];
        float4 bi = *(const float4*)&bias[d];
        v[i].x = a.x + b.x + r.x + bi.x;
        v[i].y = a.y + b.y + r.y + bi.y;
        v[i].z = a.z + b.z + r.z + bi.z;
        v[i].w = a.w + b.w + r.w + bi.w;
        s  += v[i].x + v[i].y + v[i].z + v[i].w;
        s2 += v[i].x * v[i].x + v[i].y * v[i].y + v[i].z * v[i].z + v[i].w * v[i].w;
    }
#pragma unroll
    for (int o = 16; o > 0; o >>= 1) {
        s  += __shfl_xor_sync(0xffffffffu, s,  o);
        s2 += __shfl_xor_sync(0xffffffffu, s2, o);
    }
    const float mu   = s * (1.f / DIM);
    const float rstd = rsqrtf(s2 * (1.f / DIM) - mu * mu + 1e-6f);

#pragma unroll
    for (int i = 0; i < 6; ++i) {
        const int d = lane * 4 + i * 128;
        float4 g = *(const float4*)&gam[d];
        float4 be = *(const float4*)&bet[d];
        float4 r;
        r.x = (v[i].x - mu) * rstd * g.x + be.x;
        r.y = (v[i].y - mu) * rstd * g.y + be.y;
        r.z = (v[i].z - mu) * rstd * g.z + be.z;
        r.w = (v[i].w - mu) * rstd * g.w + be.w;
        *(float4*)&out[rb + d] = r;
        if (H16) {
            uint2 u = make_uint2(hpack(r.x, r.y), hpack(r.z, r.w));
            ((uint2*)out16)[(rb + d) >> 2] = u;
        }
    }
}

// ---------------- launch ----------------
extern "C" void kernel_launch(void* const* d_in, const int* in_sizes, int n_in,
                              void* d_out, int out_size)
{
    const float* x    = (const float*)d_in[0];
    const int*   mask = (const int*)  d_in[1];
    const float* Wq   = (const float*)d_in[2];
    const float* bq   = (const float*)d_in[3];
    const float* Wk   = (const float*)d_in[4];
    const float* bk   = (const float*)d_in[5];
    const float* Wv   = (const float*)d_in[6];
    const float* bv   = (const float*)d_in[7];
    const float* Wo   = (const float*)d_in[8];
    const float* bo   = (const float*)d_in[9];
    const float* W1   = (const float*)d_in[10];
    const float* b1   = (const float*)d_in[11];
    const float* W2   = (const float*)d_in[12];
    const float* b2   = (const float*)d_in[13];
    const float* g1   = (const float*)d_in[14];
    const float* be1  = (const float*)d_in[15];
    const float* g2   = (const float*)d_in[16];
    const float* be2  = (const float*)d_in[17];
    float* out = (float*)d_out;

    __half *x16, *q16, *k16, *v16, *attn16, *h16, *ff16;
    unsigned *wq, *wk, *wv, *wo, *w1, *w2;
    float *t1, *h;
    cudaGetSymbolAddress((void**)&x16,    g_x16);
    cudaGetSymbolAddress((void**)&q16,    g_q16);
    cudaGetSymbolAddress((void**)&k16,    g_k16);
    cudaGetSymbolAddress((void**)&v16,    g_v16);
    cudaGetSymbolAddress((void**)&attn16, g_attn16);
    cudaGetSymbolAddress((void**)&h16,    g_h16);
    cudaGetSymbolAddress((void**)&ff16,   g_ff16);
    cudaGetSymbolAddress((void**)&wq,     g_wq);
    cudaGetSymbolAddress((void**)&wk,     g_wk);
    cudaGetSymbolAddress((void**)&wv,     g_wv);
    cudaGetSymbolAddress((void**)&wo,     g_wo);
    cudaGetSymbolAddress((void**)&w1,     g_w1);
    cudaGetSymbolAddress((void**)&w2,     g_w2);
    cudaGetSymbolAddress((void**)&t1,     g_t1);
    cudaGetSymbolAddress((void**)&h,      g_h);

    static bool attr_done = false;
    if (!attr_done) {
        cudaFuncSetAttribute(qkv16,       cudaFuncAttributeMaxDynamicSharedMemorySize, GS64);
        cudaFuncSetAttribute(ffn1_g,      cudaFuncAttributeMaxDynamicSharedMemorySize, GS64);
        cudaFuncSetAttribute(tgsk<DIM>,   cudaFuncAttributeMaxDynamicSharedMemorySize, GS64);
        cudaFuncSetAttribute(tgsk<FFDIM>, cudaFuncAttributeMaxDynamicSharedMemorySize, GS64);
        cudaFuncSetAttribute(attn_tc,     cudaFuncAttributeMaxDynamicSharedMemorySize, ATT_SMEM);
        attr_done = true;
    }

    // fused conversions / packing
    prep<<<PREP_BLOCKS, 256>>>(x, x16, Wq, Wk, Wv, Wo, wq, wk, wv, wo, W1, w1, W2, w2);

    // fused QKV -> fp16 [B,S,D]   (BM=64, 4-stage)
    qkv16<<<dim3(18, ROWS / 64), 256, GS64>>>(x16, wq, wk, wv, bq, bk, bv, q16, k16, v16);

    // fp16 flash attention -> fp16 [B,S,D]
    attn_tc<<<BATCH * NH * (SEQ / 128), 256, ATT_SMEM>>>(q16, k16, v16, mask, attn16);

    // O projection split-K (partials), LN1 fused add (p0+p1+x+bo)
    tgsk<DIM><<<dim3(DIM / 128, ROWS / 64, 2), 256, GS64>>>(attn16, wo, t1);
    ln_fuse<1><<<ROWS / 8, 256>>>(t1, t1 + RD, x, bo, g1, be1, h, h16);

    // FFN1 (gelu, fp16 out)   (BM=64, 4-stage)
    ffn1_g<<<dim3(FFDIM / 128, ROWS / 64), 256, GS64>>>(h16, w1, b1, ff16);

    // FFN2 split-K (partials), LN2 fused add (p0+p1+h+b2)
    tgsk<FFDIM><<<dim3(DIM / 128, ROWS / 64, 2), 256, GS64>>>(ff16, w2, t1);
    ln_fuse<0><<<ROWS / 8, 256>>>(t1, t1 + RD, h, b2, g2, be2, out, nullptr);
}